// round 7
// baseline (speedup 1.0000x reference)
#include <cuda_runtime.h>
#include <math_constants.h>

// ---------------------------------------------------------------------------
// CasualAttention via packed fp32x2 FMA (Blackwell FFMA2) + double buffering.
// B=4, S=2048, D=1024, fp32. Same 4-launch pipeline as R2:
//   1) qkv_kernel    : C[8192,3072] = X @ [Wq|Wk|Wv]
//   2) scores_kernel : per-batch Q K^T * scale, lower-triangular tiles only
//   3) softmax_kernel: causal row softmax (zeros above diagonal)
//   4) av_kernel     : P @ V, K-loop truncated at causal bound
// Inner loops use fma.rn.f32x2 (2 fp32 FMA / instr) with the A operand stored
// duplicated in smem so the broadcast pair {a,a} is a plain 64-bit LDS.
// ---------------------------------------------------------------------------

#define BM 128
#define BN 128
#define BK 16
#define TM 8
#define TN 8

static constexpr int Bb = 4;
static constexpr int S  = 2048;
static constexpr int D  = 1024;
static constexpr int M1 = Bb * S;   // 8192
static constexpr int N1 = 3 * D;    // 3072

// Scratch (__device__ globals: allocation-free rule)
__device__ float g_q[M1 * D];
__device__ float g_k[M1 * D];
__device__ float g_v[M1 * D];
__device__ float g_p[(size_t)Bb * S * S];

typedef unsigned long long u64;

__device__ __forceinline__ void ffma2(u64& d, u64 a, u64 b) {
    // d.lo = a.lo*b.lo + d.lo ; d.hi = a.hi*b.hi + d.hi   (SASS FFMA2)
    asm("fma.rn.f32x2 %0, %1, %2, %0;" : "+l"(d) : "l"(a), "l"(b));
}
__device__ __forceinline__ float f_lo(u64 v) { return __uint_as_float((unsigned)v); }
__device__ __forceinline__ float f_hi(u64 v) { return __uint_as_float((unsigned)(v >> 32)); }

// ---------------------------------------------------------------------------
// Shared-memory tile loaders (register-staged for double buffering)
// ---------------------------------------------------------------------------

// A-side: 128 rows x 16 k, loaded as float4 along k, scattered transposed and
// DUPLICATED into As[kk][2m]=As[kk][2m+1]=A[m][kk].
__device__ __forceinline__ void load_a_regs(const float* __restrict__ src, int ld,
                                            int row0, int k0, int t, float4 (&r)[2]) {
    #pragma unroll
    for (int it = 0; it < 2; it++) {
        int idx = t + it * 256;            // 0..511
        int m   = idx >> 2;                // 0..127
        int kq  = (idx & 3) * 4;           // 0,4,8,12
        r[it] = *(const float4*)(src + (size_t)(row0 + m) * ld + k0 + kq);
    }
}
__device__ __forceinline__ void store_a_dup(float (&As)[BK][2 * BM], int t,
                                            const float4 (&r)[2]) {
    #pragma unroll
    for (int it = 0; it < 2; it++) {
        int idx = t + it * 256;
        int m   = idx >> 2;
        int kq  = (idx & 3) * 4;
        *(float2*)&As[kq + 0][2 * m] = make_float2(r[it].x, r[it].x);
        *(float2*)&As[kq + 1][2 * m] = make_float2(r[it].y, r[it].y);
        *(float2*)&As[kq + 2][2 * m] = make_float2(r[it].z, r[it].z);
        *(float2*)&As[kq + 3][2 * m] = make_float2(r[it].w, r[it].w);
    }
}

// B-side, row-major source (W for qkv, V for av): Bs[row][c] = B[k0+row][col0+c]
__device__ __forceinline__ void load_b_rows(const float* __restrict__ src, int ld,
                                            int k0, int col0, int t, float4 (&r)[2]) {
    #pragma unroll
    for (int it = 0; it < 2; it++) {
        int idx = t + it * 256;
        int row = idx >> 5;                // 0..15
        int c   = (idx & 31) * 4;          // 0..124
        r[it] = *(const float4*)(src + (size_t)(k0 + row) * ld + col0 + c);
    }
}
__device__ __forceinline__ void store_b_rows(float (&Bs)[BK][BN], int t,
                                             const float4 (&r)[2]) {
    #pragma unroll
    for (int it = 0; it < 2; it++) {
        int idx = t + it * 256;
        int row = idx >> 5;
        int c   = (idx & 31) * 4;
        *(float4*)&Bs[row][c] = r[it];
    }
}

// B-side, k-contiguous source (K matrix for scores): transposed scatter.
__device__ __forceinline__ void store_b_trans(float (&Bs)[BK][BN], int t,
                                              const float4 (&r)[2]) {
    #pragma unroll
    for (int it = 0; it < 2; it++) {
        int idx = t + it * 256;
        int n   = idx >> 2;                // 0..127
        int kq  = (idx & 3) * 4;
        Bs[kq + 0][n] = r[it].x;
        Bs[kq + 1][n] = r[it].y;
        Bs[kq + 2][n] = r[it].z;
        Bs[kq + 3][n] = r[it].w;
    }
}

// ---------------------------------------------------------------------------
// FFMA2 tile compute: 8x8 per thread as 8x4 fp32x2 pairs.
// ---------------------------------------------------------------------------
__device__ __forceinline__ void mma_tile(const float (&As)[BK][2 * BM],
                                         const float (&Bs)[BK][BN],
                                         int tx, int ty, u64 (&acc)[TM][TN / 2]) {
    #pragma unroll
    for (int kk = 0; kk < BK; kk++) {
        const ulonglong2* ap = (const ulonglong2*)&As[kk][2 * (ty * TM)];
        ulonglong2 av0 = ap[0], av1 = ap[1], av2 = ap[2], av3 = ap[3];
        const ulonglong2* bp = (const ulonglong2*)&Bs[kk][tx * TN];
        ulonglong2 bv0 = bp[0], bv1 = bp[1];
        u64 a2[TM] = {av0.x, av0.y, av1.x, av1.y, av2.x, av2.y, av3.x, av3.y};
        u64 b2[TN / 2] = {bv0.x, bv0.y, bv1.x, bv1.y};
        #pragma unroll
        for (int i = 0; i < TM; i++)
            #pragma unroll
            for (int j = 0; j < TN / 2; j++)
                ffma2(acc[i][j], a2[i], b2[j]);
    }
}

// ---------------------------------------------------------------------------
// Kernel 1: fused QKV projection
// ---------------------------------------------------------------------------
__global__ __launch_bounds__(256, 2) void qkv_kernel(
    const float* __restrict__ X,
    const float* __restrict__ Wq,
    const float* __restrict__ Wk,
    const float* __restrict__ Wv)
{
    __shared__ float As[2][BK][2 * BM];   // 32 KB (duplicated A)
    __shared__ float Bs[2][BK][BN];       // 16 KB

    const int n0 = blockIdx.x * BN;
    const int m0 = blockIdx.y * BM;
    const int which = n0 >> 10;
    const float* __restrict__ W = (which == 0) ? Wq : ((which == 1) ? Wk : Wv);
    float* __restrict__ Out     = (which == 0) ? g_q : ((which == 1) ? g_k : g_v);
    const int nW = n0 & (D - 1);

    const int t  = threadIdx.x;
    const int tx = t & 15;
    const int ty = t >> 4;

    u64 acc[TM][TN / 2];
    #pragma unroll
    for (int i = 0; i < TM; i++)
        #pragma unroll
        for (int j = 0; j < TN / 2; j++) acc[i][j] = 0ULL;

    float4 ra[2], rb[2];
    load_a_regs(X, D, m0, 0, t, ra);
    load_b_rows(W, D, 0, nW, t, rb);
    store_a_dup(As[0], t, ra);
    store_b_rows(Bs[0], t, rb);
    __syncthreads();

    int cur = 0;
    for (int k0 = 0; k0 < D; k0 += BK) {
        const bool has_next = (k0 + BK) < D;
        if (has_next) {
            load_a_regs(X, D, m0, k0 + BK, t, ra);
            load_b_rows(W, D, k0 + BK, nW, t, rb);
        }
        mma_tile(As[cur], Bs[cur], tx, ty, acc);
        if (has_next) {
            store_a_dup(As[cur ^ 1], t, ra);
            store_b_rows(Bs[cur ^ 1], t, rb);
        }
        __syncthreads();
        cur ^= 1;
    }

    #pragma unroll
    for (int i = 0; i < TM; i++) {
        const int gm = m0 + ty * TM + i;
        float4 v0 = make_float4(f_lo(acc[i][0]), f_hi(acc[i][0]),
                                f_lo(acc[i][1]), f_hi(acc[i][1]));
        float4 v1 = make_float4(f_lo(acc[i][2]), f_hi(acc[i][2]),
                                f_lo(acc[i][3]), f_hi(acc[i][3]));
        *(float4*)(Out + (size_t)gm * D + nW + tx * TN + 0) = v0;
        *(float4*)(Out + (size_t)gm * D + nW + tx * TN + 4) = v1;
    }
}

// ---------------------------------------------------------------------------
// Kernel 2: scores = Q K^T * scale (lower-triangular tiles only)
// ---------------------------------------------------------------------------
__global__ __launch_bounds__(256, 2) void scores_kernel()
{
    const int jt = blockIdx.x;
    const int it = blockIdx.y;
    if (jt > it) return;
    const int b  = blockIdx.z;

    const int i0 = it * BM;
    const int j0 = jt * BN;
    const float* __restrict__ Q  = g_q + (size_t)b * S * D;
    const float* __restrict__ Km = g_k + (size_t)b * S * D;
    float* __restrict__ P        = g_p + (size_t)b * S * S;

    __shared__ float As[2][BK][2 * BM];
    __shared__ float Bs[2][BK][BN];

    const int t  = threadIdx.x;
    const int tx = t & 15;
    const int ty = t >> 4;

    u64 acc[TM][TN / 2];
    #pragma unroll
    for (int i = 0; i < TM; i++)
        #pragma unroll
        for (int j = 0; j < TN / 2; j++) acc[i][j] = 0ULL;

    float4 ra[2], rb[2];
    load_a_regs(Q, D, i0, 0, t, ra);
    load_a_regs(Km, D, j0, 0, t, rb);     // K rows are k-contiguous: A-style load
    store_a_dup(As[0], t, ra);
    store_b_trans(Bs[0], t, rb);
    __syncthreads();

    int cur = 0;
    for (int k0 = 0; k0 < D; k0 += BK) {
        const bool has_next = (k0 + BK) < D;
        if (has_next) {
            load_a_regs(Q, D, i0, k0 + BK, t, ra);
            load_a_regs(Km, D, j0, k0 + BK, t, rb);
        }
        mma_tile(As[cur], Bs[cur], tx, ty, acc);
        if (has_next) {
            store_a_dup(As[cur ^ 1], t, ra);
            store_b_trans(Bs[cur ^ 1], t, rb);
        }
        __syncthreads();
        cur ^= 1;
    }

    const float scale = 0.03125f;         // 1/sqrt(1024)
    if (jt < it) {
        #pragma unroll
        for (int i = 0; i < TM; i++) {
            const int gi = i0 + ty * TM + i;
            float4 v0 = make_float4(f_lo(acc[i][0]) * scale, f_hi(acc[i][0]) * scale,
                                    f_lo(acc[i][1]) * scale, f_hi(acc[i][1]) * scale);
            float4 v1 = make_float4(f_lo(acc[i][2]) * scale, f_hi(acc[i][2]) * scale,
                                    f_lo(acc[i][3]) * scale, f_hi(acc[i][3]) * scale);
            *(float4*)(P + (size_t)gi * S + j0 + tx * TN + 0) = v0;
            *(float4*)(P + (size_t)gi * S + j0 + tx * TN + 4) = v1;
        }
    } else {
        #pragma unroll
        for (int i = 0; i < TM; i++) {
            const int gi = i0 + ty * TM + i;
            float vals[TN] = {f_lo(acc[i][0]), f_hi(acc[i][0]), f_lo(acc[i][1]), f_hi(acc[i][1]),
                              f_lo(acc[i][2]), f_hi(acc[i][2]), f_lo(acc[i][3]), f_hi(acc[i][3])};
            #pragma unroll
            for (int j = 0; j < TN; j++) {
                const int gj = j0 + tx * TN + j;
                if (gj <= gi) P[(size_t)gi * S + gj] = vals[j] * scale;
            }
        }
    }
}

// ---------------------------------------------------------------------------
// Kernel 3: causal row softmax (zeros above diagonal)
// ---------------------------------------------------------------------------
__global__ __launch_bounds__(256) void softmax_kernel()
{
    const int r = blockIdx.x;
    const int i = r & (S - 1);
    float* __restrict__ row = g_p + (size_t)r * S;
    const int t = threadIdx.x;

    float v[8];
    float mx = -CUDART_INF_F;
    #pragma unroll
    for (int k = 0; k < 8; k++) {
        const int j = t + k * 256;
        v[k] = (j <= i) ? row[j] : -CUDART_INF_F;
        mx = fmaxf(mx, v[k]);
    }

    __shared__ float red[256];
    red[t] = mx;
    __syncthreads();
    #pragma unroll
    for (int s = 128; s > 0; s >>= 1) {
        if (t < s) red[t] = fmaxf(red[t], red[t + s]);
        __syncthreads();
    }
    mx = red[0];
    __syncthreads();

    float sum = 0.f;
    #pragma unroll
    for (int k = 0; k < 8; k++) {
        v[k] = __expf(v[k] - mx);
        sum += v[k];
    }
    red[t] = sum;
    __syncthreads();
    #pragma unroll
    for (int s = 128; s > 0; s >>= 1) {
        if (t < s) red[t] += red[t + s];
        __syncthreads();
    }
    const float inv = 1.0f / red[0];

    #pragma unroll
    for (int k = 0; k < 8; k++) {
        const int j = t + k * 256;
        row[j] = v[k] * inv;
    }
}

// ---------------------------------------------------------------------------
// Kernel 4: out = P @ V (causally truncated K-loop)
// ---------------------------------------------------------------------------
__global__ __launch_bounds__(256, 2) void av_kernel(float* __restrict__ OutAll)
{
    const int nt = blockIdx.x;
    const int mt = blockIdx.y;
    const int b  = blockIdx.z;
    const int m0 = mt * BM;
    const int n0 = nt * BN;

    const float* __restrict__ P = g_p + (size_t)b * S * S;
    const float* __restrict__ V = g_v + (size_t)b * S * D;
    float* __restrict__ O       = OutAll + (size_t)b * S * D;

    __shared__ float As[2][BK][2 * BM];
    __shared__ float Bs[2][BK][BN];

    const int t  = threadIdx.x;
    const int tx = t & 15;
    const int ty = t >> 4;

    u64 acc[TM][TN / 2];
    #pragma unroll
    for (int i = 0; i < TM; i++)
        #pragma unroll
        for (int j = 0; j < TN / 2; j++) acc[i][j] = 0ULL;

    const int kmax = m0 + BM;             // probs zero beyond the diagonal

    float4 ra[2], rb[2];
    load_a_regs(P, S, m0, 0, t, ra);
    load_b_rows(V, D, 0, n0, t, rb);
    store_a_dup(As[0], t, ra);
    store_b_rows(Bs[0], t, rb);
    __syncthreads();

    int cur = 0;
    for (int k0 = 0; k0 < kmax; k0 += BK) {
        const bool has_next = (k0 + BK) < kmax;
        if (has_next) {
            load_a_regs(P, S, m0, k0 + BK, t, ra);
            load_b_rows(V, D, k0 + BK, n0, t, rb);
        }
        mma_tile(As[cur], Bs[cur], tx, ty, acc);
        if (has_next) {
            store_a_dup(As[cur ^ 1], t, ra);
            store_b_rows(Bs[cur ^ 1], t, rb);
        }
        __syncthreads();
        cur ^= 1;
    }

    #pragma unroll
    for (int i = 0; i < TM; i++) {
        const int gm = m0 + ty * TM + i;
        float4 v0 = make_float4(f_lo(acc[i][0]), f_hi(acc[i][0]),
                                f_lo(acc[i][1]), f_hi(acc[i][1]));
        float4 v1 = make_float4(f_lo(acc[i][2]), f_hi(acc[i][2]),
                                f_lo(acc[i][3]), f_hi(acc[i][3]));
        *(float4*)(O + (size_t)gm * D + n0 + tx * TN + 0) = v0;
        *(float4*)(O + (size_t)gm * D + n0 + tx * TN + 4) = v1;
    }
}

// ---------------------------------------------------------------------------
extern "C" void kernel_launch(void* const* d_in, const int* in_sizes, int n_in,
                              void* d_out, int out_size)
{
    const float* x  = (const float*)d_in[0];
    const float* Wq = (const float*)d_in[1];
    const float* Wk = (const float*)d_in[2];
    const float* Wv = (const float*)d_in[3];
    float* out      = (float*)d_out;

    qkv_kernel<<<dim3(N1 / BN, M1 / BM), 256>>>(x, Wq, Wk, Wv);
    scores_kernel<<<dim3(S / BN, S / BM, Bb), 256>>>();
    softmax_kernel<<<Bb * S, 256>>>();
    av_kernel<<<dim3(D / BN, S / BM, Bb), 256>>>(out);
}

// round 8
// speedup vs baseline: 1.0558x; 1.0558x over previous
#include <cuda_runtime.h>
#include <math_constants.h>

// ---------------------------------------------------------------------------
// CasualAttention via packed fp32x2 FMA (Blackwell FFMA2) + double buffering.
// B=4, S=2048, D=1024, fp32. Same 4-launch pipeline as R2:
//   1) qkv_kernel    : C[8192,3072] = X @ [Wq|Wk|Wv]
//   2) scores_kernel : per-batch Q K^T * scale, lower-triangular tiles only
//   3) softmax_kernel: causal row softmax (zeros above diagonal)
//   4) av_kernel     : P @ V, K-loop truncated at causal bound
// Inner loops use fma.rn.f32x2 (2 fp32 FMA / instr) with the A operand stored
// duplicated in smem so the broadcast pair {a,a} is a plain 64-bit LDS.
// ---------------------------------------------------------------------------

#define BM 128
#define BN 128
#define BK 16
#define TM 8
#define TN 8

static constexpr int Bb = 4;
static constexpr int S  = 2048;
static constexpr int D  = 1024;
static constexpr int M1 = Bb * S;   // 8192
static constexpr int N1 = 3 * D;    // 3072

// Scratch (__device__ globals: allocation-free rule)
__device__ float g_q[M1 * D];
__device__ float g_k[M1 * D];
__device__ float g_v[M1 * D];
__device__ float g_p[(size_t)Bb * S * S];

typedef unsigned long long u64;

__device__ __forceinline__ void ffma2(u64& d, u64 a, u64 b) {
    // d.lo = a.lo*b.lo + d.lo ; d.hi = a.hi*b.hi + d.hi   (SASS FFMA2)
    asm("fma.rn.f32x2 %0, %1, %2, %0;" : "+l"(d) : "l"(a), "l"(b));
}
__device__ __forceinline__ float f_lo(u64 v) { return __uint_as_float((unsigned)v); }
__device__ __forceinline__ float f_hi(u64 v) { return __uint_as_float((unsigned)(v >> 32)); }

// ---------------------------------------------------------------------------
// Shared-memory tile loaders (register-staged for double buffering)
// ---------------------------------------------------------------------------

// A-side: 128 rows x 16 k, loaded as float4 along k, scattered transposed and
// DUPLICATED into As[kk][2m]=As[kk][2m+1]=A[m][kk].
__device__ __forceinline__ void load_a_regs(const float* __restrict__ src, int ld,
                                            int row0, int k0, int t, float4 (&r)[2]) {
    #pragma unroll
    for (int it = 0; it < 2; it++) {
        int idx = t + it * 256;            // 0..511
        int m   = idx >> 2;                // 0..127
        int kq  = (idx & 3) * 4;           // 0,4,8,12
        r[it] = *(const float4*)(src + (size_t)(row0 + m) * ld + k0 + kq);
    }
}
__device__ __forceinline__ void store_a_dup(float (&As)[BK][2 * BM], int t,
                                            const float4 (&r)[2]) {
    #pragma unroll
    for (int it = 0; it < 2; it++) {
        int idx = t + it * 256;
        int m   = idx >> 2;
        int kq  = (idx & 3) * 4;
        *(float2*)&As[kq + 0][2 * m] = make_float2(r[it].x, r[it].x);
        *(float2*)&As[kq + 1][2 * m] = make_float2(r[it].y, r[it].y);
        *(float2*)&As[kq + 2][2 * m] = make_float2(r[it].z, r[it].z);
        *(float2*)&As[kq + 3][2 * m] = make_float2(r[it].w, r[it].w);
    }
}

// B-side, row-major source (W for qkv, V for av): Bs[row][c] = B[k0+row][col0+c]
__device__ __forceinline__ void load_b_rows(const float* __restrict__ src, int ld,
                                            int k0, int col0, int t, float4 (&r)[2]) {
    #pragma unroll
    for (int it = 0; it < 2; it++) {
        int idx = t + it * 256;
        int row = idx >> 5;                // 0..15
        int c   = (idx & 31) * 4;          // 0..124
        r[it] = *(const float4*)(src + (size_t)(k0 + row) * ld + col0 + c);
    }
}
__device__ __forceinline__ void store_b_rows(float (&Bs)[BK][BN], int t,
                                             const float4 (&r)[2]) {
    #pragma unroll
    for (int it = 0; it < 2; it++) {
        int idx = t + it * 256;
        int row = idx >> 5;
        int c   = (idx & 31) * 4;
        *(float4*)&Bs[row][c] = r[it];
    }
}

// B-side, k-contiguous source (K matrix for scores): transposed scatter.
__device__ __forceinline__ void store_b_trans(float (&Bs)[BK][BN], int t,
                                              const float4 (&r)[2]) {
    #pragma unroll
    for (int it = 0; it < 2; it++) {
        int idx = t + it * 256;
        int n   = idx >> 2;                // 0..127
        int kq  = (idx & 3) * 4;
        Bs[kq + 0][n] = r[it].x;
        Bs[kq + 1][n] = r[it].y;
        Bs[kq + 2][n] = r[it].z;
        Bs[kq + 3][n] = r[it].w;
    }
}

// ---------------------------------------------------------------------------
// FFMA2 tile compute: 8x8 per thread as 8x4 fp32x2 pairs.
// ---------------------------------------------------------------------------
__device__ __forceinline__ void mma_tile(const float (&As)[BK][2 * BM],
                                         const float (&Bs)[BK][BN],
                                         int tx, int ty, u64 (&acc)[TM][TN / 2]) {
    #pragma unroll
    for (int kk = 0; kk < BK; kk++) {
        const ulonglong2* ap = (const ulonglong2*)&As[kk][2 * (ty * TM)];
        ulonglong2 av0 = ap[0], av1 = ap[1], av2 = ap[2], av3 = ap[3];
        const ulonglong2* bp = (const ulonglong2*)&Bs[kk][tx * TN];
        ulonglong2 bv0 = bp[0], bv1 = bp[1];
        u64 a2[TM] = {av0.x, av0.y, av1.x, av1.y, av2.x, av2.y, av3.x, av3.y};
        u64 b2[TN / 2] = {bv0.x, bv0.y, bv1.x, bv1.y};
        #pragma unroll
        for (int i = 0; i < TM; i++)
            #pragma unroll
            for (int j = 0; j < TN / 2; j++)
                ffma2(acc[i][j], a2[i], b2[j]);
    }
}

// ---------------------------------------------------------------------------
// Kernel 1: fused QKV projection
// ---------------------------------------------------------------------------
__global__ __launch_bounds__(256, 2) void qkv_kernel(
    const float* __restrict__ X,
    const float* __restrict__ Wq,
    const float* __restrict__ Wk,
    const float* __restrict__ Wv)
{
    __shared__ float As[2][BK][2 * BM];   // 32 KB (duplicated A)
    __shared__ float Bs[2][BK][BN];       // 16 KB

    const int n0 = blockIdx.x * BN;
    const int m0 = blockIdx.y * BM;
    const int which = n0 >> 10;
    const float* __restrict__ W = (which == 0) ? Wq : ((which == 1) ? Wk : Wv);
    float* __restrict__ Out     = (which == 0) ? g_q : ((which == 1) ? g_k : g_v);
    const int nW = n0 & (D - 1);

    const int t  = threadIdx.x;
    const int tx = t & 15;
    const int ty = t >> 4;

    u64 acc[TM][TN / 2];
    #pragma unroll
    for (int i = 0; i < TM; i++)
        #pragma unroll
        for (int j = 0; j < TN / 2; j++) acc[i][j] = 0ULL;

    float4 ra[2], rb[2];
    load_a_regs(X, D, m0, 0, t, ra);
    load_b_rows(W, D, 0, nW, t, rb);
    store_a_dup(As[0], t, ra);
    store_b_rows(Bs[0], t, rb);
    __syncthreads();

    int cur = 0;
    for (int k0 = 0; k0 < D; k0 += BK) {
        const bool has_next = (k0 + BK) < D;
        if (has_next) {
            load_a_regs(X, D, m0, k0 + BK, t, ra);
            load_b_rows(W, D, k0 + BK, nW, t, rb);
        }
        mma_tile(As[cur], Bs[cur], tx, ty, acc);
        if (has_next) {
            store_a_dup(As[cur ^ 1], t, ra);
            store_b_rows(Bs[cur ^ 1], t, rb);
        }
        __syncthreads();
        cur ^= 1;
    }

    #pragma unroll
    for (int i = 0; i < TM; i++) {
        const int gm = m0 + ty * TM + i;
        float4 v0 = make_float4(f_lo(acc[i][0]), f_hi(acc[i][0]),
                                f_lo(acc[i][1]), f_hi(acc[i][1]));
        float4 v1 = make_float4(f_lo(acc[i][2]), f_hi(acc[i][2]),
                                f_lo(acc[i][3]), f_hi(acc[i][3]));
        *(float4*)(Out + (size_t)gm * D + nW + tx * TN + 0) = v0;
        *(float4*)(Out + (size_t)gm * D + nW + tx * TN + 4) = v1;
    }
}

// ---------------------------------------------------------------------------
// Kernel 2: scores = Q K^T * scale (lower-triangular tiles only)
// ---------------------------------------------------------------------------
__global__ __launch_bounds__(256, 2) void scores_kernel()
{
    const int jt = blockIdx.x;
    const int it = blockIdx.y;
    if (jt > it) return;
    const int b  = blockIdx.z;

    const int i0 = it * BM;
    const int j0 = jt * BN;
    const float* __restrict__ Q  = g_q + (size_t)b * S * D;
    const float* __restrict__ Km = g_k + (size_t)b * S * D;
    float* __restrict__ P        = g_p + (size_t)b * S * S;

    __shared__ float As[2][BK][2 * BM];
    __shared__ float Bs[2][BK][BN];

    const int t  = threadIdx.x;
    const int tx = t & 15;
    const int ty = t >> 4;

    u64 acc[TM][TN / 2];
    #pragma unroll
    for (int i = 0; i < TM; i++)
        #pragma unroll
        for (int j = 0; j < TN / 2; j++) acc[i][j] = 0ULL;

    float4 ra[2], rb[2];
    load_a_regs(Q, D, i0, 0, t, ra);
    load_a_regs(Km, D, j0, 0, t, rb);     // K rows are k-contiguous: A-style load
    store_a_dup(As[0], t, ra);
    store_b_trans(Bs[0], t, rb);
    __syncthreads();

    int cur = 0;
    for (int k0 = 0; k0 < D; k0 += BK) {
        const bool has_next = (k0 + BK) < D;
        if (has_next) {
            load_a_regs(Q, D, i0, k0 + BK, t, ra);
            load_a_regs(Km, D, j0, k0 + BK, t, rb);
        }
        mma_tile(As[cur], Bs[cur], tx, ty, acc);
        if (has_next) {
            store_a_dup(As[cur ^ 1], t, ra);
            store_b_trans(Bs[cur ^ 1], t, rb);
        }
        __syncthreads();
        cur ^= 1;
    }

    const float scale = 0.03125f;         // 1/sqrt(1024)
    if (jt < it) {
        #pragma unroll
        for (int i = 0; i < TM; i++) {
            const int gi = i0 + ty * TM + i;
            float4 v0 = make_float4(f_lo(acc[i][0]) * scale, f_hi(acc[i][0]) * scale,
                                    f_lo(acc[i][1]) * scale, f_hi(acc[i][1]) * scale);
            float4 v1 = make_float4(f_lo(acc[i][2]) * scale, f_hi(acc[i][2]) * scale,
                                    f_lo(acc[i][3]) * scale, f_hi(acc[i][3]) * scale);
            *(float4*)(P + (size_t)gi * S + j0 + tx * TN + 0) = v0;
            *(float4*)(P + (size_t)gi * S + j0 + tx * TN + 4) = v1;
        }
    } else {
        #pragma unroll
        for (int i = 0; i < TM; i++) {
            const int gi = i0 + ty * TM + i;
            float vals[TN] = {f_lo(acc[i][0]), f_hi(acc[i][0]), f_lo(acc[i][1]), f_hi(acc[i][1]),
                              f_lo(acc[i][2]), f_hi(acc[i][2]), f_lo(acc[i][3]), f_hi(acc[i][3])};
            #pragma unroll
            for (int j = 0; j < TN; j++) {
                const int gj = j0 + tx * TN + j;
                if (gj <= gi) P[(size_t)gi * S + gj] = vals[j] * scale;
            }
        }
    }
}

// ---------------------------------------------------------------------------
// Kernel 3: causal row softmax (zeros above diagonal)
// ---------------------------------------------------------------------------
__global__ __launch_bounds__(256) void softmax_kernel()
{
    const int r = blockIdx.x;
    const int i = r & (S - 1);
    float* __restrict__ row = g_p + (size_t)r * S;
    const int t = threadIdx.x;

    float v[8];
    float mx = -CUDART_INF_F;
    #pragma unroll
    for (int k = 0; k < 8; k++) {
        const int j = t + k * 256;
        v[k] = (j <= i) ? row[j] : -CUDART_INF_F;
        mx = fmaxf(mx, v[k]);
    }

    __shared__ float red[256];
    red[t] = mx;
    __syncthreads();
    #pragma unroll
    for (int s = 128; s > 0; s >>= 1) {
        if (t < s) red[t] = fmaxf(red[t], red[t + s]);
        __syncthreads();
    }
    mx = red[0];
    __syncthreads();

    float sum = 0.f;
    #pragma unroll
    for (int k = 0; k < 8; k++) {
        v[k] = __expf(v[k] - mx);
        sum += v[k];
    }
    red[t] = sum;
    __syncthreads();
    #pragma unroll
    for (int s = 128; s > 0; s >>= 1) {
        if (t < s) red[t] += red[t + s];
        __syncthreads();
    }
    const float inv = 1.0f / red[0];

    #pragma unroll
    for (int k = 0; k < 8; k++) {
        const int j = t + k * 256;
        row[j] = v[k] * inv;
    }
}

// ---------------------------------------------------------------------------
// Kernel 4: out = P @ V (causally truncated K-loop)
// ---------------------------------------------------------------------------
__global__ __launch_bounds__(256, 2) void av_kernel(float* __restrict__ OutAll)
{
    const int nt = blockIdx.x;
    const int mt = blockIdx.y;
    const int b  = blockIdx.z;
    const int m0 = mt * BM;
    const int n0 = nt * BN;

    const float* __restrict__ P = g_p + (size_t)b * S * S;
    const float* __restrict__ V = g_v + (size_t)b * S * D;
    float* __restrict__ O       = OutAll + (size_t)b * S * D;

    __shared__ float As[2][BK][2 * BM];
    __shared__ float Bs[2][BK][BN];

    const int t  = threadIdx.x;
    const int tx = t & 15;
    const int ty = t >> 4;

    u64 acc[TM][TN / 2];
    #pragma unroll
    for (int i = 0; i < TM; i++)
        #pragma unroll
        for (int j = 0; j < TN / 2; j++) acc[i][j] = 0ULL;

    const int kmax = m0 + BM;             // probs zero beyond the diagonal

    float4 ra[2], rb[2];
    load_a_regs(P, S, m0, 0, t, ra);
    load_b_rows(V, D, 0, n0, t, rb);
    store_a_dup(As[0], t, ra);
    store_b_rows(Bs[0], t, rb);
    __syncthreads();

    int cur = 0;
    for (int k0 = 0; k0 < kmax; k0 += BK) {
        const bool has_next = (k0 + BK) < kmax;
        if (has_next) {
            load_a_regs(P, S, m0, k0 + BK, t, ra);
            load_b_rows(V, D, k0 + BK, n0, t, rb);
        }
        mma_tile(As[cur], Bs[cur], tx, ty, acc);
        if (has_next) {
            store_a_dup(As[cur ^ 1], t, ra);
            store_b_rows(Bs[cur ^ 1], t, rb);
        }
        __syncthreads();
        cur ^= 1;
    }

    #pragma unroll
    for (int i = 0; i < TM; i++) {
        const int gm = m0 + ty * TM + i;
        float4 v0 = make_float4(f_lo(acc[i][0]), f_hi(acc[i][0]),
                                f_lo(acc[i][1]), f_hi(acc[i][1]));
        float4 v1 = make_float4(f_lo(acc[i][2]), f_hi(acc[i][2]),
                                f_lo(acc[i][3]), f_hi(acc[i][3]));
        *(float4*)(O + (size_t)gm * D + n0 + tx * TN + 0) = v0;
        *(float4*)(O + (size_t)gm * D + n0 + tx * TN + 4) = v1;
    }
}

// ---------------------------------------------------------------------------
extern "C" void kernel_launch(void* const* d_in, const int* in_sizes, int n_in,
                              void* d_out, int out_size)
{
    const float* x  = (const float*)d_in[0];
    const float* Wq = (const float*)d_in[1];
    const float* Wk = (const float*)d_in[2];
    const float* Wv = (const float*)d_in[3];
    float* out      = (float*)d_out;

    qkv_kernel<<<dim3(N1 / BN, M1 / BM), 256>>>(x, Wq, Wk, Wv);
    scores_kernel<<<dim3(S / BN, S / BM, Bb), 256>>>();
    softmax_kernel<<<Bb * S, 256>>>();
    av_kernel<<<dim3(D / BN, S / BM, Bb), 256>>>(out);
}

// round 9
// speedup vs baseline: 1.0569x; 1.0010x over previous
#include <cuda_runtime.h>
#include <math_constants.h>

// ---------------------------------------------------------------------------
// CasualAttention via packed fp32x2 FMA (Blackwell FFMA2) + double buffering.
// B=4, S=2048, D=1024, fp32. Same 4-launch pipeline as R2:
//   1) qkv_kernel    : C[8192,3072] = X @ [Wq|Wk|Wv]
//   2) scores_kernel : per-batch Q K^T * scale, lower-triangular tiles only
//   3) softmax_kernel: causal row softmax (zeros above diagonal)
//   4) av_kernel     : P @ V, K-loop truncated at causal bound
// Inner loops use fma.rn.f32x2 (2 fp32 FMA / instr) with the A operand stored
// duplicated in smem so the broadcast pair {a,a} is a plain 64-bit LDS.
// ---------------------------------------------------------------------------

#define BM 128
#define BN 128
#define BK 16
#define TM 8
#define TN 8

static constexpr int Bb = 4;
static constexpr int S  = 2048;
static constexpr int D  = 1024;
static constexpr int M1 = Bb * S;   // 8192
static constexpr int N1 = 3 * D;    // 3072

// Scratch (__device__ globals: allocation-free rule)
__device__ float g_q[M1 * D];
__device__ float g_k[M1 * D];
__device__ float g_v[M1 * D];
__device__ float g_p[(size_t)Bb * S * S];

typedef unsigned long long u64;

__device__ __forceinline__ void ffma2(u64& d, u64 a, u64 b) {
    // d.lo = a.lo*b.lo + d.lo ; d.hi = a.hi*b.hi + d.hi   (SASS FFMA2)
    asm("fma.rn.f32x2 %0, %1, %2, %0;" : "+l"(d) : "l"(a), "l"(b));
}
__device__ __forceinline__ float f_lo(u64 v) { return __uint_as_float((unsigned)v); }
__device__ __forceinline__ float f_hi(u64 v) { return __uint_as_float((unsigned)(v >> 32)); }

// ---------------------------------------------------------------------------
// Shared-memory tile loaders (register-staged for double buffering)
// ---------------------------------------------------------------------------

// A-side: 128 rows x 16 k, loaded as float4 along k, scattered transposed and
// DUPLICATED into As[kk][2m]=As[kk][2m+1]=A[m][kk].
__device__ __forceinline__ void load_a_regs(const float* __restrict__ src, int ld,
                                            int row0, int k0, int t, float4 (&r)[2]) {
    #pragma unroll
    for (int it = 0; it < 2; it++) {
        int idx = t + it * 256;            // 0..511
        int m   = idx >> 2;                // 0..127
        int kq  = (idx & 3) * 4;           // 0,4,8,12
        r[it] = *(const float4*)(src + (size_t)(row0 + m) * ld + k0 + kq);
    }
}
__device__ __forceinline__ void store_a_dup(float (&As)[BK][2 * BM], int t,
                                            const float4 (&r)[2]) {
    #pragma unroll
    for (int it = 0; it < 2; it++) {
        int idx = t + it * 256;
        int m   = idx >> 2;
        int kq  = (idx & 3) * 4;
        *(float2*)&As[kq + 0][2 * m] = make_float2(r[it].x, r[it].x);
        *(float2*)&As[kq + 1][2 * m] = make_float2(r[it].y, r[it].y);
        *(float2*)&As[kq + 2][2 * m] = make_float2(r[it].z, r[it].z);
        *(float2*)&As[kq + 3][2 * m] = make_float2(r[it].w, r[it].w);
    }
}

// B-side, row-major source (W for qkv, V for av): Bs[row][c] = B[k0+row][col0+c]
__device__ __forceinline__ void load_b_rows(const float* __restrict__ src, int ld,
                                            int k0, int col0, int t, float4 (&r)[2]) {
    #pragma unroll
    for (int it = 0; it < 2; it++) {
        int idx = t + it * 256;
        int row = idx >> 5;                // 0..15
        int c   = (idx & 31) * 4;          // 0..124
        r[it] = *(const float4*)(src + (size_t)(k0 + row) * ld + col0 + c);
    }
}
__device__ __forceinline__ void store_b_rows(float (&Bs)[BK][BN], int t,
                                             const float4 (&r)[2]) {
    #pragma unroll
    for (int it = 0; it < 2; it++) {
        int idx = t + it * 256;
        int row = idx >> 5;
        int c   = (idx & 31) * 4;
        *(float4*)&Bs[row][c] = r[it];
    }
}

// B-side, k-contiguous source (K matrix for scores): transposed scatter.
__device__ __forceinline__ void store_b_trans(float (&Bs)[BK][BN], int t,
                                              const float4 (&r)[2]) {
    #pragma unroll
    for (int it = 0; it < 2; it++) {
        int idx = t + it * 256;
        int n   = idx >> 2;                // 0..127
        int kq  = (idx & 3) * 4;
        Bs[kq + 0][n] = r[it].x;
        Bs[kq + 1][n] = r[it].y;
        Bs[kq + 2][n] = r[it].z;
        Bs[kq + 3][n] = r[it].w;
    }
}

// ---------------------------------------------------------------------------
// FFMA2 tile compute: 8x8 per thread as 8x4 fp32x2 pairs.
// ---------------------------------------------------------------------------
__device__ __forceinline__ void mma_tile(const float (&As)[BK][2 * BM],
                                         const float (&Bs)[BK][BN],
                                         int tx, int ty, u64 (&acc)[TM][TN / 2]) {
    #pragma unroll
    for (int kk = 0; kk < BK; kk++) {
        const ulonglong2* ap = (const ulonglong2*)&As[kk][2 * (ty * TM)];
        ulonglong2 av0 = ap[0], av1 = ap[1], av2 = ap[2], av3 = ap[3];
        const ulonglong2* bp = (const ulonglong2*)&Bs[kk][tx * TN];
        ulonglong2 bv0 = bp[0], bv1 = bp[1];
        u64 a2[TM] = {av0.x, av0.y, av1.x, av1.y, av2.x, av2.y, av3.x, av3.y};
        u64 b2[TN / 2] = {bv0.x, bv0.y, bv1.x, bv1.y};
        #pragma unroll
        for (int i = 0; i < TM; i++)
            #pragma unroll
            for (int j = 0; j < TN / 2; j++)
                ffma2(acc[i][j], a2[i], b2[j]);
    }
}

// ---------------------------------------------------------------------------
// Kernel 1: fused QKV projection
// ---------------------------------------------------------------------------
__global__ __launch_bounds__(256, 2) void qkv_kernel(
    const float* __restrict__ X,
    const float* __restrict__ Wq,
    const float* __restrict__ Wk,
    const float* __restrict__ Wv)
{
    __shared__ float As[2][BK][2 * BM];   // 32 KB (duplicated A)
    __shared__ float Bs[2][BK][BN];       // 16 KB

    const int n0 = blockIdx.x * BN;
    const int m0 = blockIdx.y * BM;
    const int which = n0 >> 10;
    const float* __restrict__ W = (which == 0) ? Wq : ((which == 1) ? Wk : Wv);
    float* __restrict__ Out     = (which == 0) ? g_q : ((which == 1) ? g_k : g_v);
    const int nW = n0 & (D - 1);

    const int t  = threadIdx.x;
    const int tx = t & 15;
    const int ty = t >> 4;

    u64 acc[TM][TN / 2];
    #pragma unroll
    for (int i = 0; i < TM; i++)
        #pragma unroll
        for (int j = 0; j < TN / 2; j++) acc[i][j] = 0ULL;

    float4 ra[2], rb[2];
    load_a_regs(X, D, m0, 0, t, ra);
    load_b_rows(W, D, 0, nW, t, rb);
    store_a_dup(As[0], t, ra);
    store_b_rows(Bs[0], t, rb);
    __syncthreads();

    int cur = 0;
    for (int k0 = 0; k0 < D; k0 += BK) {
        const bool has_next = (k0 + BK) < D;
        if (has_next) {
            load_a_regs(X, D, m0, k0 + BK, t, ra);
            load_b_rows(W, D, k0 + BK, nW, t, rb);
        }
        mma_tile(As[cur], Bs[cur], tx, ty, acc);
        if (has_next) {
            store_a_dup(As[cur ^ 1], t, ra);
            store_b_rows(Bs[cur ^ 1], t, rb);
        }
        __syncthreads();
        cur ^= 1;
    }

    #pragma unroll
    for (int i = 0; i < TM; i++) {
        const int gm = m0 + ty * TM + i;
        float4 v0 = make_float4(f_lo(acc[i][0]), f_hi(acc[i][0]),
                                f_lo(acc[i][1]), f_hi(acc[i][1]));
        float4 v1 = make_float4(f_lo(acc[i][2]), f_hi(acc[i][2]),
                                f_lo(acc[i][3]), f_hi(acc[i][3]));
        *(float4*)(Out + (size_t)gm * D + nW + tx * TN + 0) = v0;
        *(float4*)(Out + (size_t)gm * D + nW + tx * TN + 4) = v1;
    }
}

// ---------------------------------------------------------------------------
// Kernel 2: scores = Q K^T * scale (lower-triangular tiles only)
// ---------------------------------------------------------------------------
__global__ __launch_bounds__(256, 2) void scores_kernel()
{
    const int jt = blockIdx.x;
    const int it = blockIdx.y;
    if (jt > it) return;
    const int b  = blockIdx.z;

    const int i0 = it * BM;
    const int j0 = jt * BN;
    const float* __restrict__ Q  = g_q + (size_t)b * S * D;
    const float* __restrict__ Km = g_k + (size_t)b * S * D;
    float* __restrict__ P        = g_p + (size_t)b * S * S;

    __shared__ float As[2][BK][2 * BM];
    __shared__ float Bs[2][BK][BN];

    const int t  = threadIdx.x;
    const int tx = t & 15;
    const int ty = t >> 4;

    u64 acc[TM][TN / 2];
    #pragma unroll
    for (int i = 0; i < TM; i++)
        #pragma unroll
        for (int j = 0; j < TN / 2; j++) acc[i][j] = 0ULL;

    float4 ra[2], rb[2];
    load_a_regs(Q, D, i0, 0, t, ra);
    load_a_regs(Km, D, j0, 0, t, rb);     // K rows are k-contiguous: A-style load
    store_a_dup(As[0], t, ra);
    store_b_trans(Bs[0], t, rb);
    __syncthreads();

    int cur = 0;
    for (int k0 = 0; k0 < D; k0 += BK) {
        const bool has_next = (k0 + BK) < D;
        if (has_next) {
            load_a_regs(Q, D, i0, k0 + BK, t, ra);
            load_a_regs(Km, D, j0, k0 + BK, t, rb);
        }
        mma_tile(As[cur], Bs[cur], tx, ty, acc);
        if (has_next) {
            store_a_dup(As[cur ^ 1], t, ra);
            store_b_trans(Bs[cur ^ 1], t, rb);
        }
        __syncthreads();
        cur ^= 1;
    }

    const float scale = 0.03125f;         // 1/sqrt(1024)
    if (jt < it) {
        #pragma unroll
        for (int i = 0; i < TM; i++) {
            const int gi = i0 + ty * TM + i;
            float4 v0 = make_float4(f_lo(acc[i][0]) * scale, f_hi(acc[i][0]) * scale,
                                    f_lo(acc[i][1]) * scale, f_hi(acc[i][1]) * scale);
            float4 v1 = make_float4(f_lo(acc[i][2]) * scale, f_hi(acc[i][2]) * scale,
                                    f_lo(acc[i][3]) * scale, f_hi(acc[i][3]) * scale);
            *(float4*)(P + (size_t)gi * S + j0 + tx * TN + 0) = v0;
            *(float4*)(P + (size_t)gi * S + j0 + tx * TN + 4) = v1;
        }
    } else {
        #pragma unroll
        for (int i = 0; i < TM; i++) {
            const int gi = i0 + ty * TM + i;
            float vals[TN] = {f_lo(acc[i][0]), f_hi(acc[i][0]), f_lo(acc[i][1]), f_hi(acc[i][1]),
                              f_lo(acc[i][2]), f_hi(acc[i][2]), f_lo(acc[i][3]), f_hi(acc[i][3])};
            #pragma unroll
            for (int j = 0; j < TN; j++) {
                const int gj = j0 + tx * TN + j;
                if (gj <= gi) P[(size_t)gi * S + gj] = vals[j] * scale;
            }
        }
    }
}

// ---------------------------------------------------------------------------
// Kernel 3: causal row softmax (zeros above diagonal)
// ---------------------------------------------------------------------------
__global__ __launch_bounds__(256) void softmax_kernel()
{
    const int r = blockIdx.x;
    const int i = r & (S - 1);
    float* __restrict__ row = g_p + (size_t)r * S;
    const int t = threadIdx.x;

    float v[8];
    float mx = -CUDART_INF_F;
    #pragma unroll
    for (int k = 0; k < 8; k++) {
        const int j = t + k * 256;
        v[k] = (j <= i) ? row[j] : -CUDART_INF_F;
        mx = fmaxf(mx, v[k]);
    }

    __shared__ float red[256];
    red[t] = mx;
    __syncthreads();
    #pragma unroll
    for (int s = 128; s > 0; s >>= 1) {
        if (t < s) red[t] = fmaxf(red[t], red[t + s]);
        __syncthreads();
    }
    mx = red[0];
    __syncthreads();

    float sum = 0.f;
    #pragma unroll
    for (int k = 0; k < 8; k++) {
        v[k] = __expf(v[k] - mx);
        sum += v[k];
    }
    red[t] = sum;
    __syncthreads();
    #pragma unroll
    for (int s = 128; s > 0; s >>= 1) {
        if (t < s) red[t] += red[t + s];
        __syncthreads();
    }
    const float inv = 1.0f / red[0];

    #pragma unroll
    for (int k = 0; k < 8; k++) {
        const int j = t + k * 256;
        row[j] = v[k] * inv;
    }
}

// ---------------------------------------------------------------------------
// Kernel 4: out = P @ V (causally truncated K-loop)
// ---------------------------------------------------------------------------
__global__ __launch_bounds__(256, 2) void av_kernel(float* __restrict__ OutAll)
{
    const int nt = blockIdx.x;
    const int mt = blockIdx.y;
    const int b  = blockIdx.z;
    const int m0 = mt * BM;
    const int n0 = nt * BN;

    const float* __restrict__ P = g_p + (size_t)b * S * S;
    const float* __restrict__ V = g_v + (size_t)b * S * D;
    float* __restrict__ O       = OutAll + (size_t)b * S * D;

    __shared__ float As[2][BK][2 * BM];
    __shared__ float Bs[2][BK][BN];

    const int t  = threadIdx.x;
    const int tx = t & 15;
    const int ty = t >> 4;

    u64 acc[TM][TN / 2];
    #pragma unroll
    for (int i = 0; i < TM; i++)
        #pragma unroll
        for (int j = 0; j < TN / 2; j++) acc[i][j] = 0ULL;

    const int kmax = m0 + BM;             // probs zero beyond the diagonal

    float4 ra[2], rb[2];
    load_a_regs(P, S, m0, 0, t, ra);
    load_b_rows(V, D, 0, n0, t, rb);
    store_a_dup(As[0], t, ra);
    store_b_rows(Bs[0], t, rb);
    __syncthreads();

    int cur = 0;
    for (int k0 = 0; k0 < kmax; k0 += BK) {
        const bool has_next = (k0 + BK) < kmax;
        if (has_next) {
            load_a_regs(P, S, m0, k0 + BK, t, ra);
            load_b_rows(V, D, k0 + BK, n0, t, rb);
        }
        mma_tile(As[cur], Bs[cur], tx, ty, acc);
        if (has_next) {
            store_a_dup(As[cur ^ 1], t, ra);
            store_b_rows(Bs[cur ^ 1], t, rb);
        }
        __syncthreads();
        cur ^= 1;
    }

    #pragma unroll
    for (int i = 0; i < TM; i++) {
        const int gm = m0 + ty * TM + i;
        float4 v0 = make_float4(f_lo(acc[i][0]), f_hi(acc[i][0]),
                                f_lo(acc[i][1]), f_hi(acc[i][1]));
        float4 v1 = make_float4(f_lo(acc[i][2]), f_hi(acc[i][2]),
                                f_lo(acc[i][3]), f_hi(acc[i][3]));
        *(float4*)(O + (size_t)gm * D + n0 + tx * TN + 0) = v0;
        *(float4*)(O + (size_t)gm * D + n0 + tx * TN + 4) = v1;
    }
}

// ---------------------------------------------------------------------------
extern "C" void kernel_launch(void* const* d_in, const int* in_sizes, int n_in,
                              void* d_out, int out_size)
{
    const float* x  = (const float*)d_in[0];
    const float* Wq = (const float*)d_in[1];
    const float* Wk = (const float*)d_in[2];
    const float* Wv = (const float*)d_in[3];
    float* out      = (float*)d_out;

    qkv_kernel<<<dim3(N1 / BN, M1 / BM), 256>>>(x, Wq, Wk, Wv);
    scores_kernel<<<dim3(S / BN, S / BM, Bb), 256>>>();
    softmax_kernel<<<Bb * S, 256>>>();
    av_kernel<<<dim3(D / BN, S / BM, Bb), 256>>>(out);
}

// round 11
// speedup vs baseline: 3.3381x; 3.1586x over previous
#include <cuda_runtime.h>
#include <cuda_fp16.h>
#include <math_constants.h>
#include <cstdint>

// ---------------------------------------------------------------------------
// CasualAttention via warp-level HMMA (mma.sync m16n8k16 f16->f32) with
// split-fp16 (hi+lo, 3 products) for fp32-grade accuracy. B=4,S=2048,D=1024.
// NOTE: harness compiles at virtual arch compute_103 (no 'a'), so tcgen05 is
// unavailable; mma.sync/ldmatrix/cp.async (sm_80 baseline) are the fast path.
//
// Pipeline:
//   0a) split_x     : X fp32 -> Xhi/Xlo fp16
//   0b) transpose_w : W[k][n] -> Wt[n][k] hi/lo fp16
//   1)  qkv_gemm    : C = X @ W; epilogue emits Q/K/V hi/lo fp16
//   2)  scores_gemm : Q K^T * scale (lower tiles) -> g_p fp32 (no mask needed)
//   3)  softmax     : causal softmax; emits P hi/lo fp16 (zeros above diag)
//   4)  av_gemm     : P @ V (V read [k][n] via ldmatrix.trans) -> out fp32
//
// GEMM core: CTA 128x128, 8 warps (64x32 each), K-chunk 64, cp.async double
// buffering, ldmatrix x4 fragments, 48 HMMA per warp per k-step-16.
// ---------------------------------------------------------------------------

static constexpr int Bb = 4;
static constexpr int S  = 2048;
static constexpr int D  = 1024;
static constexpr int M1 = Bb * S;          // 8192

// fp16 split operand storage (__device__ globals; allocation-free rule)
__device__ __half g_xh[M1 * D], g_xl[M1 * D];
__device__ __half g_wth[3 * D * D], g_wtl[3 * D * D];   // Wt[n][k]
__device__ __half g_qh[M1 * D], g_ql[M1 * D];
__device__ __half g_kh[M1 * D], g_kl[M1 * D];
__device__ __half g_vh[M1 * D], g_vl[M1 * D];
__device__ float  g_p [(size_t)M1 * S];                 // fp32 scores
__device__ __half g_ph[(size_t)M1 * S], g_pl[(size_t)M1 * S];

// smem geometry: A-type tile [128 rows][64 fp16] pitch 72 elems (144B);
// B-trans tile [64 rows][128 fp16] pitch 136 elems (272B).
static constexpr int A_TILE_B  = 128 * 144;   // 18432
static constexpr int STAGE_B   = 4 * A_TILE_B;            // Ah|Al|Bh|Bl = 73728
static constexpr int SMEM_BYTES = 2 * STAGE_B;            // 147456

// ---------------------------------------------------------------------------
// PTX helpers (all sm_80-baseline instructions)
// ---------------------------------------------------------------------------
__device__ __forceinline__ uint32_t smem_u32(const void* p) {
    uint32_t a;
    asm("{ .reg .u64 t; cvta.to.shared.u64 t, %1; cvt.u32.u64 %0, t; }"
        : "=r"(a) : "l"(p));
    return a;
}
__device__ __forceinline__ void cp16(uint32_t s, const void* g) {
    asm volatile("cp.async.cg.shared.global [%0], [%1], 16;\n" :: "r"(s), "l"(g));
}
__device__ __forceinline__ void cp_commit() {
    asm volatile("cp.async.commit_group;\n" ::: "memory");
}
__device__ __forceinline__ void ldsm4(uint32_t (&r)[4], uint32_t a) {
    asm volatile("ldmatrix.sync.aligned.m8n8.x4.shared.b16 {%0,%1,%2,%3}, [%4];"
                 : "=r"(r[0]), "=r"(r[1]), "=r"(r[2]), "=r"(r[3]) : "r"(a));
}
__device__ __forceinline__ void ldsm4t(uint32_t (&r)[4], uint32_t a) {
    asm volatile("ldmatrix.sync.aligned.m8n8.x4.trans.shared.b16 {%0,%1,%2,%3}, [%4];"
                 : "=r"(r[0]), "=r"(r[1]), "=r"(r[2]), "=r"(r[3]) : "r"(a));
}
__device__ __forceinline__ void mma_f16(float (&d)[4], const uint32_t (&a)[4],
                                        uint32_t b0, uint32_t b1) {
    asm volatile(
        "mma.sync.aligned.m16n8k16.row.col.f32.f16.f16.f32 "
        "{%0,%1,%2,%3}, {%4,%5,%6,%7}, {%8,%9}, {%0,%1,%2,%3};"
        : "+f"(d[0]), "+f"(d[1]), "+f"(d[2]), "+f"(d[3])
        : "r"(a[0]), "r"(a[1]), "r"(a[2]), "r"(a[3]), "r"(b0), "r"(b1));
}

// ---------------------------------------------------------------------------
// cp.async tile loaders
// ---------------------------------------------------------------------------
// [128 rows][64 fp16] <- src rows row0.., cols k0.. (row-major, leading dim ld)
__device__ __forceinline__ void cpa_tile(uint32_t dst, const __half* __restrict__ src,
                                         int ld, int row0, int k0, int t) {
    #pragma unroll
    for (int it = 0; it < 4; it++) {
        int idx = t + it * 256;                 // 0..1023
        int row = idx >> 3, u = idx & 7;        // 8 x 16B per row
        cp16(dst + row * 144 + u * 16, src + (size_t)(row0 + row) * ld + k0 + u * 8);
    }
}
// [64 k-rows][128 fp16] <- src[k0+row][n0..] (for B = V, k-major rows)
__device__ __forceinline__ void cpa_tile_t(uint32_t dst, const __half* __restrict__ src,
                                           int ld, int k0, int n0, int t) {
    #pragma unroll
    for (int it = 0; it < 4; it++) {
        int idx = t + it * 256;
        int row = idx >> 4, u = idx & 15;       // 16 x 16B per row
        cp16(dst + row * 272 + u * 16, src + (size_t)(k0 + row) * ld + n0 + u * 8);
    }
}

// ---------------------------------------------------------------------------
// Compute one K-chunk (64) from stage sb into acc[ms][ns][4].
// Warp layout: wm = wid>>2 (m 64), wn = wid&3 (n 32).
// ---------------------------------------------------------------------------
template <bool BTRANS>
__device__ __forceinline__ void compute_stage(uint32_t sb, int wid, int lane,
                                              float (&acc)[4][4][4]) {
    const int wm = wid >> 2, wn = wid & 3;

    // per-lane ldmatrix base addresses
    const uint32_t aRow = wm * 64 + (lane & 7) + ((lane >> 3) & 1) * 8;
    const uint32_t aCol = (lane >> 4) * 16;
    const uint32_t aH = sb + 0 * A_TILE_B + aRow * 144 + aCol;
    const uint32_t aL = sb + 1 * A_TILE_B + aRow * 144 + aCol;

    uint32_t bH, bL;
    if (!BTRANS) {      // B stored [n][k]
        const uint32_t bRow = wn * 32 + (lane & 7) + ((lane >> 4) & 1) * 8;
        const uint32_t bCol = ((lane >> 3) & 1) * 16;
        bH = sb + 2 * A_TILE_B + bRow * 144 + bCol;
        bL = sb + 3 * A_TILE_B + bRow * 144 + bCol;
    } else {            // B stored [k][n], use ldmatrix.trans
        const uint32_t bRow = (lane & 7) + ((lane >> 3) & 1) * 8;
        const uint32_t bCol = wn * 64 + ((lane >> 4) & 1) * 16;
        bH = sb + 2 * A_TILE_B + bRow * 272 + bCol;
        bL = sb + 3 * A_TILE_B + bRow * 272 + bCol;
    }

    #pragma unroll
    for (int ks = 0; ks < 4; ks++) {
        uint32_t ah[4][4], al[4][4], bh[2][4], bl[2][4];
        #pragma unroll
        for (int ms = 0; ms < 4; ms++) {
            ldsm4(ah[ms], aH + ms * 16 * 144 + ks * 32);
            ldsm4(al[ms], aL + ms * 16 * 144 + ks * 32);
        }
        #pragma unroll
        for (int np = 0; np < 2; np++) {
            if (!BTRANS) {
                ldsm4(bh[np], bH + np * 16 * 144 + ks * 32);
                ldsm4(bl[np], bL + np * 16 * 144 + ks * 32);
            } else {
                ldsm4t(bh[np], bH + np * 32 + ks * 16 * 272);
                ldsm4t(bl[np], bL + np * 32 + ks * 16 * 272);
            }
        }
        #pragma unroll
        for (int ms = 0; ms < 4; ms++)
            #pragma unroll
            for (int ns = 0; ns < 4; ns++) {
                const uint32_t b0h = bh[ns >> 1][(ns & 1) * 2 + 0];
                const uint32_t b1h = bh[ns >> 1][(ns & 1) * 2 + 1];
                const uint32_t b0l = bl[ns >> 1][(ns & 1) * 2 + 0];
                const uint32_t b1l = bl[ns >> 1][(ns & 1) * 2 + 1];
                mma_f16(acc[ms][ns], ah[ms], b0h, b1h);   // hh
                mma_f16(acc[ms][ns], ah[ms], b0l, b1l);   // hl
                mma_f16(acc[ms][ns], al[ms], b0h, b1h);   // lh
            }
    }
}

// ---------------------------------------------------------------------------
// GEMM mainloop: cp.async double-buffered over nchunks K-chunks of 64.
// ---------------------------------------------------------------------------
template <bool BTRANS>
__device__ __forceinline__ void gemm_main(
    const __half* __restrict__ Ah, const __half* __restrict__ Al, int lda, int m0,
    const __half* __restrict__ Bh, const __half* __restrict__ Bl, int ldb, int n0,
    int nchunks, float (&acc)[4][4][4], char* smem)
{
    const int t = threadIdx.x, wid = t >> 5, lane = t & 31;
    const uint32_t sb = smem_u32(smem);

    #pragma unroll
    for (int i = 0; i < 4; i++)
        #pragma unroll
        for (int j = 0; j < 4; j++)
            #pragma unroll
            for (int e = 0; e < 4; e++) acc[i][j][e] = 0.f;

    auto issue = [&](int c) {
        const uint32_t st = sb + (c & 1) * STAGE_B;
        const int k0 = c * 64;
        cpa_tile(st, Ah, lda, m0, k0, t);
        cpa_tile(st + A_TILE_B, Al, lda, m0, k0, t);
        if (!BTRANS) {
            cpa_tile(st + 2 * A_TILE_B, Bh, ldb, n0, k0, t);
            cpa_tile(st + 3 * A_TILE_B, Bl, ldb, n0, k0, t);
        } else {
            cpa_tile_t(st + 2 * A_TILE_B, Bh, ldb, k0, n0, t);
            cpa_tile_t(st + 3 * A_TILE_B, Bl, ldb, k0, n0, t);
        }
        cp_commit();
    };

    issue(0);
    for (int c = 0; c < nchunks; c++) {
        if (c + 1 < nchunks) {
            issue(c + 1);
            asm volatile("cp.async.wait_group 1;\n" ::: "memory");
        } else {
            asm volatile("cp.async.wait_group 0;\n" ::: "memory");
        }
        __syncthreads();
        compute_stage<BTRANS>(sb + (c & 1) * STAGE_B, wid, lane, acc);
        __syncthreads();
    }
}

// ---------------------------------------------------------------------------
// 0a) split X -> fp16 hi/lo
// ---------------------------------------------------------------------------
__global__ __launch_bounds__(256) void split_x(const float* __restrict__ X) {
    const int i = blockIdx.x * 256 + threadIdx.x;     // one float4 per thread
    float4 v = ((const float4*)X)[i];
    float f[4] = {v.x, v.y, v.z, v.w};
    union { uint2 q; __half b[4]; } uh, ul;
    #pragma unroll
    for (int e = 0; e < 4; e++) {
        __half h = __float2half_rn(f[e]);
        uh.b[e] = h;
        ul.b[e] = __float2half_rn(f[e] - __half2float(h));
    }
    *(uint2*)(g_xh + (size_t)i * 4) = uh.q;
    *(uint2*)(g_xl + (size_t)i * 4) = ul.q;
}

// ---------------------------------------------------------------------------
// 0b) transpose + split W -> Wt[n][k] hi/lo fp16
// ---------------------------------------------------------------------------
__global__ __launch_bounds__(256) void transpose_w(const float* __restrict__ Wq,
                                                   const float* __restrict__ Wk,
                                                   const float* __restrict__ Wv) {
    const int which = blockIdx.z;
    const float* __restrict__ W = (which == 0) ? Wq : (which == 1) ? Wk : Wv;
    __shared__ float tile[32][33];
    const int n0 = blockIdx.x * 32, k0 = blockIdx.y * 32;
    const int tx = threadIdx.x & 31, ty = threadIdx.x >> 5;   // 32 x 8
    #pragma unroll
    for (int r = 0; r < 32; r += 8)
        tile[ty + r][tx] = W[(size_t)(k0 + ty + r) * D + n0 + tx];
    __syncthreads();
    #pragma unroll
    for (int r = 0; r < 32; r += 8) {
        float x = tile[tx][ty + r];             // = W[k0+tx][n0+ty+r]
        __half h = __float2half_rn(x);
        __half l = __float2half_rn(x - __half2float(h));
        size_t o = (size_t)which * D * D + (size_t)(n0 + ty + r) * D + k0 + tx;
        g_wth[o] = h;
        g_wtl[o] = l;
    }
}

// ---------------------------------------------------------------------------
// 1) QKV GEMM: C = X @ W; epilogue -> Q/K/V hi/lo fp16
// ---------------------------------------------------------------------------
extern __shared__ char dynsmem[];

__global__ __launch_bounds__(256, 1) void qkv_gemm() {
    const int n0g = blockIdx.x * 128;
    const int m0  = blockIdx.y * 128;
    const int which = n0g >> 10;
    const int nW    = n0g & (D - 1);

    float acc[4][4][4];
    gemm_main<false>(g_xh, g_xl, D, m0,
                     g_wth + (size_t)which * D * D, g_wtl + (size_t)which * D * D,
                     D, nW, D / 64, acc, dynsmem);

    __half* __restrict__ Oh = (which == 0) ? g_qh : (which == 1) ? g_kh : g_vh;
    __half* __restrict__ Ol = (which == 0) ? g_ql : (which == 1) ? g_kl : g_vl;
    const int wid = threadIdx.x >> 5, lane = threadIdx.x & 31;
    const int wm = wid >> 2, wn = wid & 3;
    #pragma unroll
    for (int ms = 0; ms < 4; ms++)
        #pragma unroll
        for (int ns = 0; ns < 4; ns++) {
            const int row = m0 + wm * 64 + ms * 16 + (lane >> 2);
            const int col = nW + wn * 32 + ns * 8 + (lane & 3) * 2;
            #pragma unroll
            for (int h = 0; h < 2; h++) {                 // row, row+8
                const float c0 = acc[ms][ns][2 * h + 0];
                const float c1 = acc[ms][ns][2 * h + 1];
                const __half h0 = __float2half_rn(c0), h1 = __float2half_rn(c1);
                const __half l0 = __float2half_rn(c0 - __half2float(h0));
                const __half l1 = __float2half_rn(c1 - __half2float(h1));
                const size_t o = (size_t)(row + 8 * h) * D + col;
                *(__half2*)(Oh + o) = __halves2half2(h0, h1);
                *(__half2*)(Ol + o) = __halves2half2(l0, l1);
            }
        }
}

// ---------------------------------------------------------------------------
// 2) scores GEMM: g_p = Q K^T * scale (lower tiles; diag garbage masked later)
// ---------------------------------------------------------------------------
__global__ __launch_bounds__(256, 1) void scores_gemm() {
    const int jt = blockIdx.x, it = blockIdx.y, b = blockIdx.z;
    if (jt > it) return;
    const int m0 = it * 128, n0 = jt * 128;
    const size_t boff = (size_t)b * S * D;

    float acc[4][4][4];
    gemm_main<false>(g_qh + boff, g_ql + boff, D, m0,
                     g_kh + boff, g_kl + boff, D, n0, D / 64, acc, dynsmem);

    float* __restrict__ P = g_p + (size_t)b * S * S;
    const float scale = 0.03125f;                  // 1/sqrt(1024)
    const int wid = threadIdx.x >> 5, lane = threadIdx.x & 31;
    const int wm = wid >> 2, wn = wid & 3;
    #pragma unroll
    for (int ms = 0; ms < 4; ms++)
        #pragma unroll
        for (int ns = 0; ns < 4; ns++) {
            const int row = m0 + wm * 64 + ms * 16 + (lane >> 2);
            const int col = n0 + wn * 32 + ns * 8 + (lane & 3) * 2;
            #pragma unroll
            for (int h = 0; h < 2; h++) {
                *(float2*)(P + (size_t)(row + 8 * h) * S + col) =
                    make_float2(acc[ms][ns][2 * h + 0] * scale,
                                acc[ms][ns][2 * h + 1] * scale);
            }
        }
}

// ---------------------------------------------------------------------------
// 3) causal softmax: g_p fp32 -> P hi/lo fp16 (zeros above diagonal)
// ---------------------------------------------------------------------------
__global__ __launch_bounds__(256) void softmax_kernel() {
    const int r = blockIdx.x;                    // b*S + i
    const int i = r & (S - 1);
    const float* __restrict__ row = g_p + (size_t)r * S;
    const int t = threadIdx.x;

    float v[8];
    float mx = -CUDART_INF_F;
    #pragma unroll
    for (int k = 0; k < 8; k++) {
        const int j = t + k * 256;
        v[k] = (j <= i) ? row[j] : -CUDART_INF_F;
        mx = fmaxf(mx, v[k]);
    }
    __shared__ float red[256];
    red[t] = mx;
    __syncthreads();
    #pragma unroll
    for (int s = 128; s > 0; s >>= 1) {
        if (t < s) red[t] = fmaxf(red[t], red[t + s]);
        __syncthreads();
    }
    mx = red[0];
    __syncthreads();

    float sum = 0.f;
    #pragma unroll
    for (int k = 0; k < 8; k++) { v[k] = __expf(v[k] - mx); sum += v[k]; }
    red[t] = sum;
    __syncthreads();
    #pragma unroll
    for (int s = 128; s > 0; s >>= 1) {
        if (t < s) red[t] += red[t + s];
        __syncthreads();
    }
    const float inv = 1.0f / red[0];

    #pragma unroll
    for (int k = 0; k < 8; k++) {
        const int j = t + k * 256;
        const float p = v[k] * inv;              // 0 above diagonal
        const __half h = __float2half_rn(p);
        g_ph[(size_t)r * S + j] = h;
        g_pl[(size_t)r * S + j] = __float2half_rn(p - __half2float(h));
    }
}

// ---------------------------------------------------------------------------
// 4) AV GEMM: out = P @ V (V read [k][n] via ldmatrix.trans), causal K bound
// ---------------------------------------------------------------------------
__global__ __launch_bounds__(256, 1) void av_gemm(float* __restrict__ OutAll) {
    const int nt = blockIdx.x, mt = blockIdx.y, b = blockIdx.z;
    const int m0 = mt * 128, n0 = nt * 128;
    const int nchunks = (m0 + 128) / 64;         // causal bound

    float acc[4][4][4];
    gemm_main<true>(g_ph + (size_t)b * S * S, g_pl + (size_t)b * S * S, S, m0,
                    g_vh + (size_t)b * S * D, g_vl + (size_t)b * S * D, D, n0,
                    nchunks, acc, dynsmem);

    float* __restrict__ O = OutAll + (size_t)b * S * D;
    const int wid = threadIdx.x >> 5, lane = threadIdx.x & 31;
    const int wm = wid >> 2, wn = wid & 3;
    #pragma unroll
    for (int ms = 0; ms < 4; ms++)
        #pragma unroll
        for (int ns = 0; ns < 4; ns++) {
            const int row = m0 + wm * 64 + ms * 16 + (lane >> 2);
            const int col = n0 + wn * 32 + ns * 8 + (lane & 3) * 2;
            #pragma unroll
            for (int h = 0; h < 2; h++) {
                *(float2*)(O + (size_t)(row + 8 * h) * D + col) =
                    make_float2(acc[ms][ns][2 * h + 0], acc[ms][ns][2 * h + 1]);
            }
        }
}

// ---------------------------------------------------------------------------
extern "C" void kernel_launch(void* const* d_in, const int* in_sizes, int n_in,
                              void* d_out, int out_size)
{
    const float* x  = (const float*)d_in[0];
    const float* Wq = (const float*)d_in[1];
    const float* Wk = (const float*)d_in[2];
    const float* Wv = (const float*)d_in[3];
    float* out      = (float*)d_out;

    cudaFuncSetAttribute(qkv_gemm,    cudaFuncAttributeMaxDynamicSharedMemorySize, SMEM_BYTES);
    cudaFuncSetAttribute(scores_gemm, cudaFuncAttributeMaxDynamicSharedMemorySize, SMEM_BYTES);
    cudaFuncSetAttribute(av_gemm,     cudaFuncAttributeMaxDynamicSharedMemorySize, SMEM_BYTES);

    split_x<<<M1 * D / 4 / 256, 256>>>(x);
    transpose_w<<<dim3(D / 32, D / 32, 3), 256>>>(Wq, Wk, Wv);
    qkv_gemm<<<dim3(3 * D / 128, M1 / 128), 256, SMEM_BYTES>>>();
    scores_gemm<<<dim3(S / 128, S / 128, Bb), 256, SMEM_BYTES>>>();
    softmax_kernel<<<M1, 256>>>();
    av_gemm<<<dim3(D / 128, S / 128, Bb), 256, SMEM_BYTES>>>(out);
}

// round 12
// speedup vs baseline: 3.5462x; 1.0623x over previous
#include <cuda_runtime.h>
#include <cuda_fp16.h>
#include <math_constants.h>
#include <cstdint>

// ---------------------------------------------------------------------------
// CasualAttention via warp-level HMMA (mma.sync m16n8k16 f16->f32), split-fp16
// (hi+lo) operands for fp32-grade accuracy. B=4, S=2048, D=1024.
// compute_103 virtual arch => sm_80-class PTX only (mma.sync/ldmatrix/cp.async).
//
// R12: 3-stage cp.async pipeline (prefetch 2 chunks), AV uses unsplit fp16 P
// (2 MMAs/step), causally-bounded softmax.
// ---------------------------------------------------------------------------

static constexpr int Bb = 4;
static constexpr int S  = 2048;
static constexpr int D  = 1024;
static constexpr int M1 = Bb * S;          // 8192

__device__ __half g_xh[M1 * D], g_xl[M1 * D];
__device__ __half g_wth[3 * D * D], g_wtl[3 * D * D];   // Wt[n][k]
__device__ __half g_qh[M1 * D], g_ql[M1 * D];
__device__ __half g_kh[M1 * D], g_kl[M1 * D];
__device__ __half g_vh[M1 * D], g_vl[M1 * D];
__device__ float  g_p [(size_t)M1 * S];                 // fp32 scores
__device__ __half g_ph[(size_t)M1 * S];                 // softmax probs (fp16)

// smem: slot = one [128][64] fp16 tile, pitch 144B (A-type) or [64][128] pitch
// 272B (B-trans type, 17408B <= slot). 4 slots per stage, 3 stages.
static constexpr int SLOT_B    = 128 * 144;             // 18432
static constexpr int STAGE_B   = 4 * SLOT_B;            // 73728
static constexpr int NSTAGE    = 3;
static constexpr int SMEM_BYTES = NSTAGE * STAGE_B;     // 221184

// ---------------------------------------------------------------------------
__device__ __forceinline__ uint32_t smem_u32(const void* p) {
    uint32_t a;
    asm("{ .reg .u64 t; cvta.to.shared.u64 t, %1; cvt.u32.u64 %0, t; }"
        : "=r"(a) : "l"(p));
    return a;
}
__device__ __forceinline__ void cp16(uint32_t s, const void* g) {
    asm volatile("cp.async.cg.shared.global [%0], [%1], 16;\n" :: "r"(s), "l"(g));
}
__device__ __forceinline__ void cp_commit() {
    asm volatile("cp.async.commit_group;\n" ::: "memory");
}
__device__ __forceinline__ void ldsm4(uint32_t (&r)[4], uint32_t a) {
    asm volatile("ldmatrix.sync.aligned.m8n8.x4.shared.b16 {%0,%1,%2,%3}, [%4];"
                 : "=r"(r[0]), "=r"(r[1]), "=r"(r[2]), "=r"(r[3]) : "r"(a));
}
__device__ __forceinline__ void ldsm4t(uint32_t (&r)[4], uint32_t a) {
    asm volatile("ldmatrix.sync.aligned.m8n8.x4.trans.shared.b16 {%0,%1,%2,%3}, [%4];"
                 : "=r"(r[0]), "=r"(r[1]), "=r"(r[2]), "=r"(r[3]) : "r"(a));
}
__device__ __forceinline__ void mma_f16(float (&d)[4], const uint32_t (&a)[4],
                                        uint32_t b0, uint32_t b1) {
    asm volatile(
        "mma.sync.aligned.m16n8k16.row.col.f32.f16.f16.f32 "
        "{%0,%1,%2,%3}, {%4,%5,%6,%7}, {%8,%9}, {%0,%1,%2,%3};"
        : "+f"(d[0]), "+f"(d[1]), "+f"(d[2]), "+f"(d[3])
        : "r"(a[0]), "r"(a[1]), "r"(a[2]), "r"(a[3]), "r"(b0), "r"(b1));
}

// ---------------------------------------------------------------------------
// cp.async tile loaders
// ---------------------------------------------------------------------------
__device__ __forceinline__ void cpa_tile(uint32_t dst, const __half* __restrict__ src,
                                         int ld, int row0, int k0, int t) {
    #pragma unroll
    for (int it = 0; it < 4; it++) {
        int idx = t + it * 256;                 // 0..1023
        int row = idx >> 3, u = idx & 7;        // 8 x 16B per row
        cp16(dst + row * 144 + u * 16, src + (size_t)(row0 + row) * ld + k0 + u * 8);
    }
}
__device__ __forceinline__ void cpa_tile_t(uint32_t dst, const __half* __restrict__ src,
                                           int ld, int k0, int n0, int t) {
    #pragma unroll
    for (int it = 0; it < 4; it++) {
        int idx = t + it * 256;
        int row = idx >> 4, u = idx & 15;       // 16 x 16B per row
        cp16(dst + row * 272 + u * 16, src + (size_t)(k0 + row) * ld + n0 + u * 8);
    }
}

// ---------------------------------------------------------------------------
// Compute one K-chunk (64) from stage sb. Warp tile 64x32 (wm=wid>>2, wn=wid&3).
// ASPLIT: A has hi+lo (3 products hh,hl,lh); else A single (2 products hh,hl).
// ---------------------------------------------------------------------------
template <bool BTRANS, bool ASPLIT>
__device__ __forceinline__ void compute_stage(uint32_t sb, int wid, int lane,
                                              float (&acc)[4][4][4]) {
    const int wm = wid >> 2, wn = wid & 3;

    const uint32_t aRow = wm * 64 + (lane & 7) + ((lane >> 3) & 1) * 8;
    const uint32_t aCol = (lane >> 4) * 16;
    const uint32_t aH = sb + 0 * SLOT_B + aRow * 144 + aCol;
    const uint32_t aL = sb + 1 * SLOT_B + aRow * 144 + aCol;

    uint32_t bH, bL;
    if (!BTRANS) {      // B stored [n][k]
        const uint32_t bRow = wn * 32 + (lane & 7) + ((lane >> 4) & 1) * 8;
        const uint32_t bCol = ((lane >> 3) & 1) * 16;
        bH = sb + 2 * SLOT_B + bRow * 144 + bCol;
        bL = sb + 3 * SLOT_B + bRow * 144 + bCol;
    } else {            // B stored [k][n], ldmatrix.trans
        const uint32_t bRow = (lane & 7) + ((lane >> 3) & 1) * 8;
        const uint32_t bCol = wn * 64 + ((lane >> 4) & 1) * 16;
        bH = sb + 2 * SLOT_B + bRow * 272 + bCol;
        bL = sb + 3 * SLOT_B + bRow * 272 + bCol;
    }

    #pragma unroll
    for (int ks = 0; ks < 4; ks++) {
        uint32_t ah[4][4], al[4][4], bh[2][4], bl[2][4];
        #pragma unroll
        for (int ms = 0; ms < 4; ms++) {
            ldsm4(ah[ms], aH + ms * 16 * 144 + ks * 32);
            if (ASPLIT) ldsm4(al[ms], aL + ms * 16 * 144 + ks * 32);
        }
        #pragma unroll
        for (int np = 0; np < 2; np++) {
            if (!BTRANS) {
                ldsm4(bh[np], bH + np * 16 * 144 + ks * 32);
                ldsm4(bl[np], bL + np * 16 * 144 + ks * 32);
            } else {
                ldsm4t(bh[np], bH + np * 32 + ks * 16 * 272);
                ldsm4t(bl[np], bL + np * 32 + ks * 16 * 272);
            }
        }
        #pragma unroll
        for (int ms = 0; ms < 4; ms++)
            #pragma unroll
            for (int ns = 0; ns < 4; ns++) {
                const uint32_t b0h = bh[ns >> 1][(ns & 1) * 2 + 0];
                const uint32_t b1h = bh[ns >> 1][(ns & 1) * 2 + 1];
                const uint32_t b0l = bl[ns >> 1][(ns & 1) * 2 + 0];
                const uint32_t b1l = bl[ns >> 1][(ns & 1) * 2 + 1];
                mma_f16(acc[ms][ns], ah[ms], b0h, b1h);             // hh
                mma_f16(acc[ms][ns], ah[ms], b0l, b1l);             // hl
                if (ASPLIT) mma_f16(acc[ms][ns], al[ms], b0h, b1h); // lh
            }
    }
}

// ---------------------------------------------------------------------------
// GEMM mainloop: 3-stage cp.async pipeline over nchunks K-chunks of 64.
// Per iter: wait(stage c) / sync / compute(c) / sync / issue(c+3).
// issue(c+3) overwrites stage c%3, guarded by the preceding sync.
// ---------------------------------------------------------------------------
template <bool BTRANS, bool ASPLIT>
__device__ __forceinline__ void gemm_main(
    const __half* __restrict__ Ah, const __half* __restrict__ Al, int lda, int m0,
    const __half* __restrict__ Bh, const __half* __restrict__ Bl, int ldb, int n0,
    int nchunks, float (&acc)[4][4][4], char* smem)
{
    const int t = threadIdx.x, wid = t >> 5, lane = t & 31;
    const uint32_t sb = smem_u32(smem);

    #pragma unroll
    for (int i = 0; i < 4; i++)
        #pragma unroll
        for (int j = 0; j < 4; j++)
            #pragma unroll
            for (int e = 0; e < 4; e++) acc[i][j][e] = 0.f;

    auto issue = [&](int c) {
        const uint32_t st = sb + (c % NSTAGE) * STAGE_B;
        const int k0 = c * 64;
        cpa_tile(st, Ah, lda, m0, k0, t);
        if (ASPLIT) cpa_tile(st + SLOT_B, Al, lda, m0, k0, t);
        if (!BTRANS) {
            cpa_tile(st + 2 * SLOT_B, Bh, ldb, n0, k0, t);
            cpa_tile(st + 3 * SLOT_B, Bl, ldb, n0, k0, t);
        } else {
            cpa_tile_t(st + 2 * SLOT_B, Bh, ldb, k0, n0, t);
            cpa_tile_t(st + 3 * SLOT_B, Bl, ldb, k0, n0, t);
        }
        cp_commit();
    };

    issue(0);
    if (nchunks > 1) issue(1);
    if (nchunks > 2) issue(2);

    for (int c = 0; c < nchunks; c++) {
        // groups newer than c that are still allowed in flight
        const int pend = ((nchunks < c + 3) ? nchunks : (c + 3)) - (c + 1);
        if (pend >= 2)      asm volatile("cp.async.wait_group 2;\n" ::: "memory");
        else if (pend == 1) asm volatile("cp.async.wait_group 1;\n" ::: "memory");
        else                asm volatile("cp.async.wait_group 0;\n" ::: "memory");
        __syncthreads();
        compute_stage<BTRANS, ASPLIT>(sb + (c % NSTAGE) * STAGE_B, wid, lane, acc);
        __syncthreads();
        if (c + 3 < nchunks) issue(c + 3);
    }
}

// ---------------------------------------------------------------------------
// 0a) split X -> fp16 hi/lo
// ---------------------------------------------------------------------------
__global__ __launch_bounds__(256) void split_x(const float* __restrict__ X) {
    const int i = blockIdx.x * 256 + threadIdx.x;
    float4 v = ((const float4*)X)[i];
    float f[4] = {v.x, v.y, v.z, v.w};
    union { uint2 q; __half b[4]; } uh, ul;
    #pragma unroll
    for (int e = 0; e < 4; e++) {
        __half h = __float2half_rn(f[e]);
        uh.b[e] = h;
        ul.b[e] = __float2half_rn(f[e] - __half2float(h));
    }
    *(uint2*)(g_xh + (size_t)i * 4) = uh.q;
    *(uint2*)(g_xl + (size_t)i * 4) = ul.q;
}

// ---------------------------------------------------------------------------
// 0b) transpose + split W -> Wt[n][k] hi/lo fp16
// ---------------------------------------------------------------------------
__global__ __launch_bounds__(256) void transpose_w(const float* __restrict__ Wq,
                                                   const float* __restrict__ Wk,
                                                   const float* __restrict__ Wv) {
    const int which = blockIdx.z;
    const float* __restrict__ W = (which == 0) ? Wq : (which == 1) ? Wk : Wv;
    __shared__ float tile[32][33];
    const int n0 = blockIdx.x * 32, k0 = blockIdx.y * 32;
    const int tx = threadIdx.x & 31, ty = threadIdx.x >> 5;   // 32 x 8
    #pragma unroll
    for (int r = 0; r < 32; r += 8)
        tile[ty + r][tx] = W[(size_t)(k0 + ty + r) * D + n0 + tx];
    __syncthreads();
    #pragma unroll
    for (int r = 0; r < 32; r += 8) {
        float x = tile[tx][ty + r];
        __half h = __float2half_rn(x);
        __half l = __float2half_rn(x - __half2float(h));
        size_t o = (size_t)which * D * D + (size_t)(n0 + ty + r) * D + k0 + tx;
        g_wth[o] = h;
        g_wtl[o] = l;
    }
}

// ---------------------------------------------------------------------------
// 1) QKV GEMM: C = X @ W; epilogue -> Q/K/V hi/lo fp16
// ---------------------------------------------------------------------------
extern __shared__ char dynsmem[];

__global__ __launch_bounds__(256, 1) void qkv_gemm() {
    const int n0g = blockIdx.x * 128;
    const int m0  = blockIdx.y * 128;
    const int which = n0g >> 10;
    const int nW    = n0g & (D - 1);

    float acc[4][4][4];
    gemm_main<false, true>(g_xh, g_xl, D, m0,
                           g_wth + (size_t)which * D * D,
                           g_wtl + (size_t)which * D * D,
                           D, nW, D / 64, acc, dynsmem);

    __half* __restrict__ Oh = (which == 0) ? g_qh : (which == 1) ? g_kh : g_vh;
    __half* __restrict__ Ol = (which == 0) ? g_ql : (which == 1) ? g_kl : g_vl;
    const int wid = threadIdx.x >> 5, lane = threadIdx.x & 31;
    const int wm = wid >> 2, wn = wid & 3;
    #pragma unroll
    for (int ms = 0; ms < 4; ms++)
        #pragma unroll
        for (int ns = 0; ns < 4; ns++) {
            const int row = m0 + wm * 64 + ms * 16 + (lane >> 2);
            const int col = nW + wn * 32 + ns * 8 + (lane & 3) * 2;
            #pragma unroll
            for (int h = 0; h < 2; h++) {
                const float c0 = acc[ms][ns][2 * h + 0];
                const float c1 = acc[ms][ns][2 * h + 1];
                const __half h0 = __float2half_rn(c0), h1 = __float2half_rn(c1);
                const __half l0 = __float2half_rn(c0 - __half2float(h0));
                const __half l1 = __float2half_rn(c1 - __half2float(h1));
                const size_t o = (size_t)(row + 8 * h) * D + col;
                *(__half2*)(Oh + o) = __halves2half2(h0, h1);
                *(__half2*)(Ol + o) = __halves2half2(l0, l1);
            }
        }
}

// ---------------------------------------------------------------------------
// 2) scores GEMM: g_p = Q K^T * scale (lower tiles only)
// ---------------------------------------------------------------------------
__global__ __launch_bounds__(256, 1) void scores_gemm() {
    const int jt = blockIdx.x, it = blockIdx.y, b = blockIdx.z;
    if (jt > it) return;
    const int m0 = it * 128, n0 = jt * 128;
    const size_t boff = (size_t)b * S * D;

    float acc[4][4][4];
    gemm_main<false, true>(g_qh + boff, g_ql + boff, D, m0,
                           g_kh + boff, g_kl + boff, D, n0, D / 64, acc, dynsmem);

    float* __restrict__ P = g_p + (size_t)b * S * S;
    const float scale = 0.03125f;                  // 1/sqrt(1024)
    const int wid = threadIdx.x >> 5, lane = threadIdx.x & 31;
    const int wm = wid >> 2, wn = wid & 3;
    #pragma unroll
    for (int ms = 0; ms < 4; ms++)
        #pragma unroll
        for (int ns = 0; ns < 4; ns++) {
            const int row = m0 + wm * 64 + ms * 16 + (lane >> 2);
            const int col = n0 + wn * 32 + ns * 8 + (lane & 3) * 2;
            #pragma unroll
            for (int h = 0; h < 2; h++) {
                *(float2*)(P + (size_t)(row + 8 * h) * S + col) =
                    make_float2(acc[ms][ns][2 * h + 0] * scale,
                                acc[ms][ns][2 * h + 1] * scale);
            }
        }
}

// ---------------------------------------------------------------------------
// 3) causal softmax: g_p fp32 -> g_ph fp16 (zeros up to 128-aligned bound)
// ---------------------------------------------------------------------------
__global__ __launch_bounds__(256) void softmax_kernel() {
    const int r = blockIdx.x;                    // b*S + i
    const int i = r & (S - 1);
    const int jmax = ((i >> 7) + 1) << 7;        // AV reads only j < jmax
    const float* __restrict__ row = g_p + (size_t)r * S;
    const int t = threadIdx.x;

    float v[8];
    float mx = -CUDART_INF_F;
    #pragma unroll
    for (int k = 0; k < 8; k++) {
        const int j = t + k * 256;
        v[k] = (j <= i) ? row[j] : -CUDART_INF_F;
        mx = fmaxf(mx, v[k]);
    }
    __shared__ float red[256];
    red[t] = mx;
    __syncthreads();
    #pragma unroll
    for (int s = 128; s > 0; s >>= 1) {
        if (t < s) red[t] = fmaxf(red[t], red[t + s]);
        __syncthreads();
    }
    mx = red[0];
    __syncthreads();

    float sum = 0.f;
    #pragma unroll
    for (int k = 0; k < 8; k++) { v[k] = __expf(v[k] - mx); sum += v[k]; }
    red[t] = sum;
    __syncthreads();
    #pragma unroll
    for (int s = 128; s > 0; s >>= 1) {
        if (t < s) red[t] += red[t + s];
        __syncthreads();
    }
    const float inv = 1.0f / red[0];

    #pragma unroll
    for (int k = 0; k < 8; k++) {
        const int j = t + k * 256;
        if (j < jmax)
            g_ph[(size_t)r * S + j] = __float2half_rn(v[k] * inv);
    }
}

// ---------------------------------------------------------------------------
// 4) AV GEMM: out = P @ V. P unsplit fp16 (2 MMAs), causal K bound.
// ---------------------------------------------------------------------------
__global__ __launch_bounds__(256, 1) void av_gemm(float* __restrict__ OutAll) {
    const int nt = blockIdx.x, mt = blockIdx.y, b = blockIdx.z;
    const int m0 = mt * 128, n0 = nt * 128;
    const int nchunks = (m0 + 128) / 64;         // causal bound

    float acc[4][4][4];
    gemm_main<true, false>(g_ph + (size_t)b * S * S, (const __half*)nullptr, S, m0,
                           g_vh + (size_t)b * S * D, g_vl + (size_t)b * S * D, D, n0,
                           nchunks, acc, dynsmem);

    float* __restrict__ O = OutAll + (size_t)b * S * D;
    const int wid = threadIdx.x >> 5, lane = threadIdx.x & 31;
    const int wm = wid >> 2, wn = wid & 3;
    #pragma unroll
    for (int ms = 0; ms < 4; ms++)
        #pragma unroll
        for (int ns = 0; ns < 4; ns++) {
            const int row = m0 + wm * 64 + ms * 16 + (lane >> 2);
            const int col = n0 + wn * 32 + ns * 8 + (lane & 3) * 2;
            #pragma unroll
            for (int h = 0; h < 2; h++) {
                *(float2*)(O + (size_t)(row + 8 * h) * D + col) =
                    make_float2(acc[ms][ns][2 * h + 0], acc[ms][ns][2 * h + 1]);
            }
        }
}

// ---------------------------------------------------------------------------
extern "C" void kernel_launch(void* const* d_in, const int* in_sizes, int n_in,
                              void* d_out, int out_size)
{
    const float* x  = (const float*)d_in[0];
    const float* Wq = (const float*)d_in[1];
    const float* Wk = (const float*)d_in[2];
    const float* Wv = (const float*)d_in[3];
    float* out      = (float*)d_out;

    cudaFuncSetAttribute(qkv_gemm,    cudaFuncAttributeMaxDynamicSharedMemorySize, SMEM_BYTES);
    cudaFuncSetAttribute(scores_gemm, cudaFuncAttributeMaxDynamicSharedMemorySize, SMEM_BYTES);
    cudaFuncSetAttribute(av_gemm,     cudaFuncAttributeMaxDynamicSharedMemorySize, SMEM_BYTES);

    split_x<<<M1 * D / 4 / 256, 256>>>(x);
    transpose_w<<<dim3(D / 32, D / 32, 3), 256>>>(Wq, Wk, Wv);
    qkv_gemm<<<dim3(3 * D / 128, M1 / 128), 256, SMEM_BYTES>>>();
    scores_gemm<<<dim3(S / 128, S / 128, Bb), 256, SMEM_BYTES>>>();
    softmax_kernel<<<M1, 256>>>();
    av_gemm<<<dim3(D / 128, S / 128, Bb), 256, SMEM_BYTES>>>(out);
}

// round 13
// speedup vs baseline: 3.6443x; 1.0276x over previous
#include <cuda_runtime.h>
#include <cuda_fp16.h>
#include <math_constants.h>
#include <cstdint>

// ---------------------------------------------------------------------------
// CasualAttention via warp-level HMMA (mma.sync m16n8k16 f16->f32), split-fp16
// (hi+lo) operands. B=4, S=2048, D=1024. compute_103 => sm_80-class PTX.
//
// R13: occupancy play. K-chunk 32, pitch-80 smem (conflict-free), 2 stages
// => 80KB smem/CTA, <=128 regs => 2 CTAs/SM (16 warps) so barrier bubbles of
// one CTA are filled by the other. Same pipeline as R12 otherwise.
// ---------------------------------------------------------------------------

static constexpr int Bb = 4;
static constexpr int S  = 2048;
static constexpr int D  = 1024;
static constexpr int M1 = Bb * S;          // 8192

__device__ __half g_xh[M1 * D], g_xl[M1 * D];
__device__ __half g_wth[3 * D * D], g_wtl[3 * D * D];   // Wt[n][k]
__device__ __half g_qh[M1 * D], g_ql[M1 * D];
__device__ __half g_kh[M1 * D], g_kl[M1 * D];
__device__ __half g_vh[M1 * D], g_vl[M1 * D];
__device__ float  g_p [(size_t)M1 * S];                 // fp32 scores
__device__ __half g_ph[(size_t)M1 * S];                 // softmax probs (fp16)

// smem: slot = [128 rows][32 fp16] pitch 80B (A-type / B-[n][k] type), or
// [32 k-rows][128 fp16] pitch 272B (B-trans, 8704B <= slot). 4 slots/stage.
static constexpr int KCHUNK   = 32;
static constexpr int SLOT_B   = 128 * 80;               // 10240
static constexpr int STAGE_B  = 4 * SLOT_B;             // 40960
static constexpr int NSTAGE   = 2;
static constexpr int SMEM_BYTES = NSTAGE * STAGE_B;     // 81920 -> 2 CTAs/SM

// ---------------------------------------------------------------------------
__device__ __forceinline__ uint32_t smem_u32(const void* p) {
    uint32_t a;
    asm("{ .reg .u64 t; cvta.to.shared.u64 t, %1; cvt.u32.u64 %0, t; }"
        : "=r"(a) : "l"(p));
    return a;
}
__device__ __forceinline__ void cp16(uint32_t s, const void* g) {
    asm volatile("cp.async.cg.shared.global [%0], [%1], 16;\n" :: "r"(s), "l"(g));
}
__device__ __forceinline__ void cp_commit() {
    asm volatile("cp.async.commit_group;\n" ::: "memory");
}
__device__ __forceinline__ void ldsm4(uint32_t (&r)[4], uint32_t a) {
    asm volatile("ldmatrix.sync.aligned.m8n8.x4.shared.b16 {%0,%1,%2,%3}, [%4];"
                 : "=r"(r[0]), "=r"(r[1]), "=r"(r[2]), "=r"(r[3]) : "r"(a));
}
__device__ __forceinline__ void ldsm4t(uint32_t (&r)[4], uint32_t a) {
    asm volatile("ldmatrix.sync.aligned.m8n8.x4.trans.shared.b16 {%0,%1,%2,%3}, [%4];"
                 : "=r"(r[0]), "=r"(r[1]), "=r"(r[2]), "=r"(r[3]) : "r"(a));
}
__device__ __forceinline__ void mma_f16(float (&d)[4], const uint32_t (&a)[4],
                                        uint32_t b0, uint32_t b1) {
    asm volatile(
        "mma.sync.aligned.m16n8k16.row.col.f32.f16.f16.f32 "
        "{%0,%1,%2,%3}, {%4,%5,%6,%7}, {%8,%9}, {%0,%1,%2,%3};"
        : "+f"(d[0]), "+f"(d[1]), "+f"(d[2]), "+f"(d[3])
        : "r"(a[0]), "r"(a[1]), "r"(a[2]), "r"(a[3]), "r"(b0), "r"(b1));
}

// ---------------------------------------------------------------------------
// cp.async tile loaders (K-chunk 32)
// ---------------------------------------------------------------------------
// [128 rows][32 fp16] <- src rows row0.., k cols k0..  (512 cp16)
__device__ __forceinline__ void cpa_tile(uint32_t dst, const __half* __restrict__ src,
                                         int ld, int row0, int k0, int t) {
    #pragma unroll
    for (int it = 0; it < 2; it++) {
        int idx = t + it * 256;                 // 0..511
        int row = idx >> 2, u = idx & 3;        // 4 x 16B per row
        cp16(dst + row * 80 + u * 16, src + (size_t)(row0 + row) * ld + k0 + u * 8);
    }
}
// [32 k-rows][128 fp16] <- src[k0+row][n0..]  (512 cp16, pitch 272)
__device__ __forceinline__ void cpa_tile_t(uint32_t dst, const __half* __restrict__ src,
                                           int ld, int k0, int n0, int t) {
    #pragma unroll
    for (int it = 0; it < 2; it++) {
        int idx = t + it * 256;
        int row = idx >> 4, u = idx & 15;       // 16 x 16B per row
        cp16(dst + row * 272 + u * 16, src + (size_t)(k0 + row) * ld + n0 + u * 8);
    }
}

// ---------------------------------------------------------------------------
// Compute one K-chunk (32) from stage sb. Warp tile 64x32 (wm=wid>>2, wn=wid&3).
// B fragments held per-ks; A fragments loaded per-ms (register pressure <=128).
// ---------------------------------------------------------------------------
template <bool BTRANS, bool ASPLIT>
__device__ __forceinline__ void compute_stage(uint32_t sb, int wid, int lane,
                                              float (&acc)[4][4][4]) {
    const int wm = wid >> 2, wn = wid & 3;

    const uint32_t aRow = wm * 64 + (lane & 7) + ((lane >> 3) & 1) * 8;
    const uint32_t aCol = (lane >> 4) * 16;
    const uint32_t aH = sb + 0 * SLOT_B + aRow * 80 + aCol;
    const uint32_t aL = sb + 1 * SLOT_B + aRow * 80 + aCol;

    uint32_t bH, bL;
    if (!BTRANS) {      // B stored [n][k]
        const uint32_t bRow = wn * 32 + (lane & 7) + ((lane >> 4) & 1) * 8;
        const uint32_t bCol = ((lane >> 3) & 1) * 16;
        bH = sb + 2 * SLOT_B + bRow * 80 + bCol;
        bL = sb + 3 * SLOT_B + bRow * 80 + bCol;
    } else {            // B stored [k][n], ldmatrix.trans
        const uint32_t bRow = (lane & 7) + ((lane >> 3) & 1) * 8;
        const uint32_t bCol = wn * 64 + ((lane >> 4) & 1) * 16;
        bH = sb + 2 * SLOT_B + bRow * 272 + bCol;
        bL = sb + 3 * SLOT_B + bRow * 272 + bCol;
    }

    #pragma unroll
    for (int ks = 0; ks < 2; ks++) {
        uint32_t bh[2][4], bl[2][4];
        #pragma unroll
        for (int np = 0; np < 2; np++) {
            if (!BTRANS) {
                ldsm4(bh[np], bH + np * 16 * 80 + ks * 32);
                ldsm4(bl[np], bL + np * 16 * 80 + ks * 32);
            } else {
                ldsm4t(bh[np], bH + np * 32 + ks * 16 * 272);
                ldsm4t(bl[np], bL + np * 32 + ks * 16 * 272);
            }
        }
        #pragma unroll
        for (int ms = 0; ms < 4; ms++) {
            uint32_t ah[4], al[4];
            ldsm4(ah, aH + ms * 16 * 80 + ks * 32);
            if (ASPLIT) ldsm4(al, aL + ms * 16 * 80 + ks * 32);
            #pragma unroll
            for (int ns = 0; ns < 4; ns++) {
                const uint32_t b0h = bh[ns >> 1][(ns & 1) * 2 + 0];
                const uint32_t b1h = bh[ns >> 1][(ns & 1) * 2 + 1];
                const uint32_t b0l = bl[ns >> 1][(ns & 1) * 2 + 0];
                const uint32_t b1l = bl[ns >> 1][(ns & 1) * 2 + 1];
                mma_f16(acc[ms][ns], ah, b0h, b1h);             // hh
                mma_f16(acc[ms][ns], ah, b0l, b1l);             // hl
                if (ASPLIT) mma_f16(acc[ms][ns], al, b0h, b1h); // lh
            }
        }
    }
}

// ---------------------------------------------------------------------------
// GEMM mainloop: 2-stage cp.async pipeline over nchunks K-chunks of 32.
// ---------------------------------------------------------------------------
template <bool BTRANS, bool ASPLIT>
__device__ __forceinline__ void gemm_main(
    const __half* __restrict__ Ah, const __half* __restrict__ Al, int lda, int m0,
    const __half* __restrict__ Bh, const __half* __restrict__ Bl, int ldb, int n0,
    int nchunks, float (&acc)[4][4][4], char* smem)
{
    const int t = threadIdx.x, wid = t >> 5, lane = t & 31;
    const uint32_t sb = smem_u32(smem);

    #pragma unroll
    for (int i = 0; i < 4; i++)
        #pragma unroll
        for (int j = 0; j < 4; j++)
            #pragma unroll
            for (int e = 0; e < 4; e++) acc[i][j][e] = 0.f;

    auto issue = [&](int c) {
        const uint32_t st = sb + (c & 1) * STAGE_B;
        const int k0 = c * KCHUNK;
        cpa_tile(st, Ah, lda, m0, k0, t);
        if (ASPLIT) cpa_tile(st + SLOT_B, Al, lda, m0, k0, t);
        if (!BTRANS) {
            cpa_tile(st + 2 * SLOT_B, Bh, ldb, n0, k0, t);
            cpa_tile(st + 3 * SLOT_B, Bl, ldb, n0, k0, t);
        } else {
            cpa_tile_t(st + 2 * SLOT_B, Bh, ldb, k0, n0, t);
            cpa_tile_t(st + 3 * SLOT_B, Bl, ldb, k0, n0, t);
        }
        cp_commit();
    };

    issue(0);
    if (nchunks > 1) issue(1);

    for (int c = 0; c < nchunks; c++) {
        if (c + 1 < nchunks) asm volatile("cp.async.wait_group 1;\n" ::: "memory");
        else                 asm volatile("cp.async.wait_group 0;\n" ::: "memory");
        __syncthreads();
        compute_stage<BTRANS, ASPLIT>(sb + (c & 1) * STAGE_B, wid, lane, acc);
        __syncthreads();
        if (c + 2 < nchunks) issue(c + 2);
    }
}

// ---------------------------------------------------------------------------
// 0a) split X -> fp16 hi/lo
// ---------------------------------------------------------------------------
__global__ __launch_bounds__(256) void split_x(const float* __restrict__ X) {
    const int i = blockIdx.x * 256 + threadIdx.x;
    float4 v = ((const float4*)X)[i];
    float f[4] = {v.x, v.y, v.z, v.w};
    union { uint2 q; __half b[4]; } uh, ul;
    #pragma unroll
    for (int e = 0; e < 4; e++) {
        __half h = __float2half_rn(f[e]);
        uh.b[e] = h;
        ul.b[e] = __float2half_rn(f[e] - __half2float(h));
    }
    *(uint2*)(g_xh + (size_t)i * 4) = uh.q;
    *(uint2*)(g_xl + (size_t)i * 4) = ul.q;
}

// ---------------------------------------------------------------------------
// 0b) transpose + split W -> Wt[n][k] hi/lo fp16
// ---------------------------------------------------------------------------
__global__ __launch_bounds__(256) void transpose_w(const float* __restrict__ Wq,
                                                   const float* __restrict__ Wk,
                                                   const float* __restrict__ Wv) {
    const int which = blockIdx.z;
    const float* __restrict__ W = (which == 0) ? Wq : (which == 1) ? Wk : Wv;
    __shared__ float tile[32][33];
    const int n0 = blockIdx.x * 32, k0 = blockIdx.y * 32;
    const int tx = threadIdx.x & 31, ty = threadIdx.x >> 5;   // 32 x 8
    #pragma unroll
    for (int r = 0; r < 32; r += 8)
        tile[ty + r][tx] = W[(size_t)(k0 + ty + r) * D + n0 + tx];
    __syncthreads();
    #pragma unroll
    for (int r = 0; r < 32; r += 8) {
        float x = tile[tx][ty + r];
        __half h = __float2half_rn(x);
        __half l = __float2half_rn(x - __half2float(h));
        size_t o = (size_t)which * D * D + (size_t)(n0 + ty + r) * D + k0 + tx;
        g_wth[o] = h;
        g_wtl[o] = l;
    }
}

// ---------------------------------------------------------------------------
// 1) QKV GEMM: C = X @ W; epilogue -> Q/K/V hi/lo fp16
// ---------------------------------------------------------------------------
extern __shared__ char dynsmem[];

__global__ __launch_bounds__(256, 2) void qkv_gemm() {
    const int n0g = blockIdx.x * 128;
    const int m0  = blockIdx.y * 128;
    const int which = n0g >> 10;
    const int nW    = n0g & (D - 1);

    float acc[4][4][4];
    gemm_main<false, true>(g_xh, g_xl, D, m0,
                           g_wth + (size_t)which * D * D,
                           g_wtl + (size_t)which * D * D,
                           D, nW, D / KCHUNK, acc, dynsmem);

    __half* __restrict__ Oh = (which == 0) ? g_qh : (which == 1) ? g_kh : g_vh;
    __half* __restrict__ Ol = (which == 0) ? g_ql : (which == 1) ? g_kl : g_vl;
    const int wid = threadIdx.x >> 5, lane = threadIdx.x & 31;
    const int wm = wid >> 2, wn = wid & 3;
    #pragma unroll
    for (int ms = 0; ms < 4; ms++)
        #pragma unroll
        for (int ns = 0; ns < 4; ns++) {
            const int row = m0 + wm * 64 + ms * 16 + (lane >> 2);
            const int col = nW + wn * 32 + ns * 8 + (lane & 3) * 2;
            #pragma unroll
            for (int h = 0; h < 2; h++) {
                const float c0 = acc[ms][ns][2 * h + 0];
                const float c1 = acc[ms][ns][2 * h + 1];
                const __half h0 = __float2half_rn(c0), h1 = __float2half_rn(c1);
                const __half l0 = __float2half_rn(c0 - __half2float(h0));
                const __half l1 = __float2half_rn(c1 - __half2float(h1));
                const size_t o = (size_t)(row + 8 * h) * D + col;
                *(__half2*)(Oh + o) = __halves2half2(h0, h1);
                *(__half2*)(Ol + o) = __halves2half2(l0, l1);
            }
        }
}

// ---------------------------------------------------------------------------
// 2) scores GEMM: g_p = Q K^T * scale (lower tiles only)
// ---------------------------------------------------------------------------
__global__ __launch_bounds__(256, 2) void scores_gemm() {
    const int jt = blockIdx.x, it = blockIdx.y, b = blockIdx.z;
    if (jt > it) return;
    const int m0 = it * 128, n0 = jt * 128;
    const size_t boff = (size_t)b * S * D;

    float acc[4][4][4];
    gemm_main<false, true>(g_qh + boff, g_ql + boff, D, m0,
                           g_kh + boff, g_kl + boff, D, n0, D / KCHUNK,
                           acc, dynsmem);

    float* __restrict__ P = g_p + (size_t)b * S * S;
    const float scale = 0.03125f;                  // 1/sqrt(1024)
    const int wid = threadIdx.x >> 5, lane = threadIdx.x & 31;
    const int wm = wid >> 2, wn = wid & 3;
    #pragma unroll
    for (int ms = 0; ms < 4; ms++)
        #pragma unroll
        for (int ns = 0; ns < 4; ns++) {
            const int row = m0 + wm * 64 + ms * 16 + (lane >> 2);
            const int col = n0 + wn * 32 + ns * 8 + (lane & 3) * 2;
            #pragma unroll
            for (int h = 0; h < 2; h++) {
                *(float2*)(P + (size_t)(row + 8 * h) * S + col) =
                    make_float2(acc[ms][ns][2 * h + 0] * scale,
                                acc[ms][ns][2 * h + 1] * scale);
            }
        }
}

// ---------------------------------------------------------------------------
// 3) causal softmax: g_p fp32 -> g_ph fp16 (zeros up to 128-aligned bound)
// ---------------------------------------------------------------------------
__global__ __launch_bounds__(256) void softmax_kernel() {
    const int r = blockIdx.x;                    // b*S + i
    const int i = r & (S - 1);
    const int jmax = ((i >> 7) + 1) << 7;        // AV reads only j < jmax
    const float* __restrict__ row = g_p + (size_t)r * S;
    const int t = threadIdx.x;

    float v[8];
    float mx = -CUDART_INF_F;
    #pragma unroll
    for (int k = 0; k < 8; k++) {
        const int j = t + k * 256;
        v[k] = (j <= i) ? row[j] : -CUDART_INF_F;
        mx = fmaxf(mx, v[k]);
    }
    __shared__ float red[256];
    red[t] = mx;
    __syncthreads();
    #pragma unroll
    for (int s = 128; s > 0; s >>= 1) {
        if (t < s) red[t] = fmaxf(red[t], red[t + s]);
        __syncthreads();
    }
    mx = red[0];
    __syncthreads();

    float sum = 0.f;
    #pragma unroll
    for (int k = 0; k < 8; k++) { v[k] = __expf(v[k] - mx); sum += v[k]; }
    red[t] = sum;
    __syncthreads();
    #pragma unroll
    for (int s = 128; s > 0; s >>= 1) {
        if (t < s) red[t] += red[t + s];
        __syncthreads();
    }
    const float inv = 1.0f / red[0];

    #pragma unroll
    for (int k = 0; k < 8; k++) {
        const int j = t + k * 256;
        if (j < jmax)
            g_ph[(size_t)r * S + j] = __float2half_rn(v[k] * inv);
    }
}

// ---------------------------------------------------------------------------
// 4) AV GEMM: out = P @ V. P unsplit fp16 (2 MMAs), causal K bound.
// ---------------------------------------------------------------------------
__global__ __launch_bounds__(256, 2) void av_gemm(float* __restrict__ OutAll) {
    const int nt = blockIdx.x, mt = blockIdx.y, b = blockIdx.z;
    const int m0 = mt * 128, n0 = nt * 128;
    const int nchunks = (m0 + 128) / KCHUNK;     // causal bound

    float acc[4][4][4];
    gemm_main<true, false>(g_ph + (size_t)b * S * S, (const __half*)nullptr, S, m0,
                           g_vh + (size_t)b * S * D, g_vl + (size_t)b * S * D, D, n0,
                           nchunks, acc, dynsmem);

    float* __restrict__ O = OutAll + (size_t)b * S * D;
    const int wid = threadIdx.x >> 5, lane = threadIdx.x & 31;
    const int wm = wid >> 2, wn = wid & 3;
    #pragma unroll
    for (int ms = 0; ms < 4; ms++)
        #pragma unroll
        for (int ns = 0; ns < 4; ns++) {
            const int row = m0 + wm * 64 + ms * 16 + (lane >> 2);
            const int col = n0 + wn * 32 + ns * 8 + (lane & 3) * 2;
            #pragma unroll
            for (int h = 0; h < 2; h++) {
                *(float2*)(O + (size_t)(row + 8 * h) * D + col) =
                    make_float2(acc[ms][ns][2 * h + 0], acc[ms][ns][2 * h + 1]);
            }
        }
}

// ---------------------------------------------------------------------------
extern "C" void kernel_launch(void* const* d_in, const int* in_sizes, int n_in,
                              void* d_out, int out_size)
{
    const float* x  = (const float*)d_in[0];
    const float* Wq = (const float*)d_in[1];
    const float* Wk = (const float*)d_in[2];
    const float* Wv = (const float*)d_in[3];
    float* out      = (float*)d_out;

    cudaFuncSetAttribute(qkv_gemm,    cudaFuncAttributeMaxDynamicSharedMemorySize, SMEM_BYTES);
    cudaFuncSetAttribute(scores_gemm, cudaFuncAttributeMaxDynamicSharedMemorySize, SMEM_BYTES);
    cudaFuncSetAttribute(av_gemm,     cudaFuncAttributeMaxDynamicSharedMemorySize, SMEM_BYTES);

    split_x<<<M1 * D / 4 / 256, 256>>>(x);
    transpose_w<<<dim3(D / 32, D / 32, 3), 256>>>(Wq, Wk, Wv);
    qkv_gemm<<<dim3(3 * D / 128, M1 / 128), 256, SMEM_BYTES>>>();
    scores_gemm<<<dim3(S / 128, S / 128, Bb), 256, SMEM_BYTES>>>();
    softmax_kernel<<<M1, 256>>>();
    av_gemm<<<dim3(D / 128, S / 128, Bb), 256, SMEM_BYTES>>>(out);
}

// round 14
// speedup vs baseline: 4.7846x; 1.3129x over previous
#include <cuda_runtime.h>
#include <cuda_fp16.h>
#include <math_constants.h>
#include <cstdint>

// ---------------------------------------------------------------------------
// CasualAttention via warp-level HMMA (mma.sync m16n8k16 f16->f32), split-fp16
// operands where precision requires. B=4, S=2048, D=1024. compute_103 =>
// sm_80-class PTX (mma.sync / ldmatrix / cp.async).
//
// R14: measured HMMA-form ceiling (~640 MAC/cyc/SM) is occupancy-invariant, so
// this round cuts MMA count instead:
//   qkv    : 2-product (Xh*Wh + Xh*Wl)      [drops Xl*Wh, +2.4e-4 per tensor]
//   scores : 3-product (full split)          [unchanged: feeds softmax exp]
//   av     : 1-product (P_fp16 * Vh)         [drops Vl]
// Inner MMAs reordered (hh x4, hl x4, lh x4 per ms) so same-acc MMAs are >=4
// instructions apart.
// ---------------------------------------------------------------------------

static constexpr int Bb = 4;
static constexpr int S  = 2048;
static constexpr int D  = 1024;
static constexpr int M1 = Bb * S;          // 8192

__device__ __half g_xh[M1 * D];
__device__ __half g_wth[3 * D * D], g_wtl[3 * D * D];   // Wt[n][k]
__device__ __half g_qh[M1 * D], g_ql[M1 * D];
__device__ __half g_kh[M1 * D], g_kl[M1 * D];
__device__ __half g_vh[M1 * D];
__device__ float  g_p [(size_t)M1 * S];                 // fp32 scores
__device__ __half g_ph[(size_t)M1 * S];                 // softmax probs (fp16)

// smem: slot = [128 rows][32 fp16] pitch 80B (A / B-[n][k]), or [32 k-rows]
// [128 fp16] pitch 272B (B-trans, 8704B <= slot). 4 slots/stage, 2 stages.
static constexpr int KCHUNK   = 32;
static constexpr int SLOT_B   = 128 * 80;               // 10240
static constexpr int STAGE_B  = 4 * SLOT_B;             // 40960
static constexpr int SMEM_BYTES = 2 * STAGE_B;          // 81920 -> 2 CTAs/SM

// ---------------------------------------------------------------------------
__device__ __forceinline__ uint32_t smem_u32(const void* p) {
    uint32_t a;
    asm("{ .reg .u64 t; cvta.to.shared.u64 t, %1; cvt.u32.u64 %0, t; }"
        : "=r"(a) : "l"(p));
    return a;
}
__device__ __forceinline__ void cp16(uint32_t s, const void* g) {
    asm volatile("cp.async.cg.shared.global [%0], [%1], 16;\n" :: "r"(s), "l"(g));
}
__device__ __forceinline__ void cp_commit() {
    asm volatile("cp.async.commit_group;\n" ::: "memory");
}
__device__ __forceinline__ void ldsm4(uint32_t (&r)[4], uint32_t a) {
    asm volatile("ldmatrix.sync.aligned.m8n8.x4.shared.b16 {%0,%1,%2,%3}, [%4];"
                 : "=r"(r[0]), "=r"(r[1]), "=r"(r[2]), "=r"(r[3]) : "r"(a));
}
__device__ __forceinline__ void ldsm4t(uint32_t (&r)[4], uint32_t a) {
    asm volatile("ldmatrix.sync.aligned.m8n8.x4.trans.shared.b16 {%0,%1,%2,%3}, [%4];"
                 : "=r"(r[0]), "=r"(r[1]), "=r"(r[2]), "=r"(r[3]) : "r"(a));
}
__device__ __forceinline__ void mma_f16(float (&d)[4], const uint32_t (&a)[4],
                                        uint32_t b0, uint32_t b1) {
    asm volatile(
        "mma.sync.aligned.m16n8k16.row.col.f32.f16.f16.f32 "
        "{%0,%1,%2,%3}, {%4,%5,%6,%7}, {%8,%9}, {%0,%1,%2,%3};"
        : "+f"(d[0]), "+f"(d[1]), "+f"(d[2]), "+f"(d[3])
        : "r"(a[0]), "r"(a[1]), "r"(a[2]), "r"(a[3]), "r"(b0), "r"(b1));
}

// ---------------------------------------------------------------------------
// cp.async tile loaders (K-chunk 32)
// ---------------------------------------------------------------------------
__device__ __forceinline__ void cpa_tile(uint32_t dst, const __half* __restrict__ src,
                                         int ld, int row0, int k0, int t) {
    #pragma unroll
    for (int it = 0; it < 2; it++) {
        int idx = t + it * 256;                 // 0..511
        int row = idx >> 2, u = idx & 3;        // 4 x 16B per row
        cp16(dst + row * 80 + u * 16, src + (size_t)(row0 + row) * ld + k0 + u * 8);
    }
}
__device__ __forceinline__ void cpa_tile_t(uint32_t dst, const __half* __restrict__ src,
                                           int ld, int k0, int n0, int t) {
    #pragma unroll
    for (int it = 0; it < 2; it++) {
        int idx = t + it * 256;
        int row = idx >> 4, u = idx & 15;       // 16 x 16B per row
        cp16(dst + row * 272 + u * 16, src + (size_t)(k0 + row) * ld + n0 + u * 8);
    }
}

// ---------------------------------------------------------------------------
// Compute one K-chunk (32). Warp tile 64x32 (wm=wid>>2, wn=wid&3).
// Products: hh always; hl if BSPLIT; lh if ASPLIT. Reordered per-ms so
// same-accumulator MMAs are 4 apart.
// ---------------------------------------------------------------------------
template <bool BTRANS, bool ASPLIT, bool BSPLIT>
__device__ __forceinline__ void compute_stage(uint32_t sb, int wid, int lane,
                                              float (&acc)[4][4][4]) {
    const int wm = wid >> 2, wn = wid & 3;

    const uint32_t aRow = wm * 64 + (lane & 7) + ((lane >> 3) & 1) * 8;
    const uint32_t aCol = (lane >> 4) * 16;
    const uint32_t aH = sb + 0 * SLOT_B + aRow * 80 + aCol;
    const uint32_t aL = sb + 1 * SLOT_B + aRow * 80 + aCol;

    uint32_t bH, bL;
    if (!BTRANS) {      // B stored [n][k]
        const uint32_t bRow = wn * 32 + (lane & 7) + ((lane >> 4) & 1) * 8;
        const uint32_t bCol = ((lane >> 3) & 1) * 16;
        bH = sb + 2 * SLOT_B + bRow * 80 + bCol;
        bL = sb + 3 * SLOT_B + bRow * 80 + bCol;
    } else {            // B stored [k][n], ldmatrix.trans
        const uint32_t bRow = (lane & 7) + ((lane >> 3) & 1) * 8;
        const uint32_t bCol = wn * 64 + ((lane >> 4) & 1) * 16;
        bH = sb + 2 * SLOT_B + bRow * 272 + bCol;
        bL = sb + 3 * SLOT_B + bRow * 272 + bCol;
    }

    #pragma unroll
    for (int ks = 0; ks < 2; ks++) {
        uint32_t bh[2][4], bl[2][4];
        #pragma unroll
        for (int np = 0; np < 2; np++) {
            if (!BTRANS) {
                ldsm4(bh[np], bH + np * 16 * 80 + ks * 32);
                if (BSPLIT) ldsm4(bl[np], bL + np * 16 * 80 + ks * 32);
            } else {
                ldsm4t(bh[np], bH + np * 32 + ks * 16 * 272);
                if (BSPLIT) ldsm4t(bl[np], bL + np * 32 + ks * 16 * 272);
            }
        }
        #pragma unroll
        for (int ms = 0; ms < 4; ms++) {
            uint32_t ah[4], al[4];
            ldsm4(ah, aH + ms * 16 * 80 + ks * 32);
            if (ASPLIT) ldsm4(al, aL + ms * 16 * 80 + ks * 32);
            #pragma unroll
            for (int ns = 0; ns < 4; ns++)       // hh: 4 independent
                mma_f16(acc[ms][ns], ah,
                        bh[ns >> 1][(ns & 1) * 2 + 0], bh[ns >> 1][(ns & 1) * 2 + 1]);
            if (BSPLIT)
                #pragma unroll
                for (int ns = 0; ns < 4; ns++)   // hl
                    mma_f16(acc[ms][ns], ah,
                            bl[ns >> 1][(ns & 1) * 2 + 0], bl[ns >> 1][(ns & 1) * 2 + 1]);
            if (ASPLIT)
                #pragma unroll
                for (int ns = 0; ns < 4; ns++)   // lh
                    mma_f16(acc[ms][ns], al,
                            bh[ns >> 1][(ns & 1) * 2 + 0], bh[ns >> 1][(ns & 1) * 2 + 1]);
        }
    }
}

// ---------------------------------------------------------------------------
// GEMM mainloop: 2-stage cp.async pipeline over nchunks K-chunks of 32.
// ---------------------------------------------------------------------------
template <bool BTRANS, bool ASPLIT, bool BSPLIT>
__device__ __forceinline__ void gemm_main(
    const __half* __restrict__ Ah, const __half* __restrict__ Al, int lda, int m0,
    const __half* __restrict__ Bh, const __half* __restrict__ Bl, int ldb, int n0,
    int nchunks, float (&acc)[4][4][4], char* smem)
{
    const int t = threadIdx.x, wid = t >> 5, lane = t & 31;
    const uint32_t sb = smem_u32(smem);

    #pragma unroll
    for (int i = 0; i < 4; i++)
        #pragma unroll
        for (int j = 0; j < 4; j++)
            #pragma unroll
            for (int e = 0; e < 4; e++) acc[i][j][e] = 0.f;

    auto issue = [&](int c) {
        const uint32_t st = sb + (c & 1) * STAGE_B;
        const int k0 = c * KCHUNK;
        cpa_tile(st, Ah, lda, m0, k0, t);
        if (ASPLIT) cpa_tile(st + SLOT_B, Al, lda, m0, k0, t);
        if (!BTRANS) {
            cpa_tile(st + 2 * SLOT_B, Bh, ldb, n0, k0, t);
            if (BSPLIT) cpa_tile(st + 3 * SLOT_B, Bl, ldb, n0, k0, t);
        } else {
            cpa_tile_t(st + 2 * SLOT_B, Bh, ldb, k0, n0, t);
            if (BSPLIT) cpa_tile_t(st + 3 * SLOT_B, Bl, ldb, k0, n0, t);
        }
        cp_commit();
    };

    issue(0);
    if (nchunks > 1) issue(1);

    for (int c = 0; c < nchunks; c++) {
        if (c + 1 < nchunks) asm volatile("cp.async.wait_group 1;\n" ::: "memory");
        else                 asm volatile("cp.async.wait_group 0;\n" ::: "memory");
        __syncthreads();
        compute_stage<BTRANS, ASPLIT, BSPLIT>(sb + (c & 1) * STAGE_B, wid, lane, acc);
        __syncthreads();
        if (c + 2 < nchunks) issue(c + 2);
    }
}

// ---------------------------------------------------------------------------
// 0a) convert X -> fp16 hi (lo no longer needed: QKV is 2-product)
// ---------------------------------------------------------------------------
__global__ __launch_bounds__(256) void split_x(const float* __restrict__ X) {
    const int i = blockIdx.x * 256 + threadIdx.x;
    float4 v = ((const float4*)X)[i];
    float f[4] = {v.x, v.y, v.z, v.w};
    union { uint2 q; __half b[4]; } uh;
    #pragma unroll
    for (int e = 0; e < 4; e++) uh.b[e] = __float2half_rn(f[e]);
    *(uint2*)(g_xh + (size_t)i * 4) = uh.q;
}

// ---------------------------------------------------------------------------
// 0b) transpose + split W -> Wt[n][k] hi/lo fp16
// ---------------------------------------------------------------------------
__global__ __launch_bounds__(256) void transpose_w(const float* __restrict__ Wq,
                                                   const float* __restrict__ Wk,
                                                   const float* __restrict__ Wv) {
    const int which = blockIdx.z;
    const float* __restrict__ W = (which == 0) ? Wq : (which == 1) ? Wk : Wv;
    __shared__ float tile[32][33];
    const int n0 = blockIdx.x * 32, k0 = blockIdx.y * 32;
    const int tx = threadIdx.x & 31, ty = threadIdx.x >> 5;   // 32 x 8
    #pragma unroll
    for (int r = 0; r < 32; r += 8)
        tile[ty + r][tx] = W[(size_t)(k0 + ty + r) * D + n0 + tx];
    __syncthreads();
    #pragma unroll
    for (int r = 0; r < 32; r += 8) {
        float x = tile[tx][ty + r];
        __half h = __float2half_rn(x);
        __half l = __float2half_rn(x - __half2float(h));
        size_t o = (size_t)which * D * D + (size_t)(n0 + ty + r) * D + k0 + tx;
        g_wth[o] = h;
        g_wtl[o] = l;
    }
}

// ---------------------------------------------------------------------------
// 1) QKV GEMM (2-product): C = Xh @ (Wh + Wl); epilogue -> Q/K hi+lo, V hi
// ---------------------------------------------------------------------------
extern __shared__ char dynsmem[];

__global__ __launch_bounds__(256, 2) void qkv_gemm() {
    const int n0g = blockIdx.x * 128;
    const int m0  = blockIdx.y * 128;
    const int which = n0g >> 10;
    const int nW    = n0g & (D - 1);

    float acc[4][4][4];
    gemm_main<false, false, true>(g_xh, (const __half*)nullptr, D, m0,
                                  g_wth + (size_t)which * D * D,
                                  g_wtl + (size_t)which * D * D,
                                  D, nW, D / KCHUNK, acc, dynsmem);

    __half* __restrict__ Oh = (which == 0) ? g_qh : (which == 1) ? g_kh : g_vh;
    __half* __restrict__ Ol = (which == 0) ? g_ql : g_kl;   // unused for V
    const int wid = threadIdx.x >> 5, lane = threadIdx.x & 31;
    const int wm = wid >> 2, wn = wid & 3;
    #pragma unroll
    for (int ms = 0; ms < 4; ms++)
        #pragma unroll
        for (int ns = 0; ns < 4; ns++) {
            const int row = m0 + wm * 64 + ms * 16 + (lane >> 2);
            const int col = nW + wn * 32 + ns * 8 + (lane & 3) * 2;
            #pragma unroll
            for (int h = 0; h < 2; h++) {
                const float c0 = acc[ms][ns][2 * h + 0];
                const float c1 = acc[ms][ns][2 * h + 1];
                const __half h0 = __float2half_rn(c0), h1 = __float2half_rn(c1);
                const size_t o = (size_t)(row + 8 * h) * D + col;
                *(__half2*)(Oh + o) = __halves2half2(h0, h1);
                if (which != 2) {
                    const __half l0 = __float2half_rn(c0 - __half2float(h0));
                    const __half l1 = __float2half_rn(c1 - __half2float(h1));
                    *(__half2*)(Ol + o) = __halves2half2(l0, l1);
                }
            }
        }
}

// ---------------------------------------------------------------------------
// 2) scores GEMM (3-product): g_p = Q K^T * scale (lower tiles only)
// ---------------------------------------------------------------------------
__global__ __launch_bounds__(256, 2) void scores_gemm() {
    const int jt = blockIdx.x, it = blockIdx.y, b = blockIdx.z;
    if (jt > it) return;
    const int m0 = it * 128, n0 = jt * 128;
    const size_t boff = (size_t)b * S * D;

    float acc[4][4][4];
    gemm_main<false, true, true>(g_qh + boff, g_ql + boff, D, m0,
                                 g_kh + boff, g_kl + boff, D, n0, D / KCHUNK,
                                 acc, dynsmem);

    float* __restrict__ P = g_p + (size_t)b * S * S;
    const float scale = 0.03125f;                  // 1/sqrt(1024)
    const int wid = threadIdx.x >> 5, lane = threadIdx.x & 31;
    const int wm = wid >> 2, wn = wid & 3;
    #pragma unroll
    for (int ms = 0; ms < 4; ms++)
        #pragma unroll
        for (int ns = 0; ns < 4; ns++) {
            const int row = m0 + wm * 64 + ms * 16 + (lane >> 2);
            const int col = n0 + wn * 32 + ns * 8 + (lane & 3) * 2;
            #pragma unroll
            for (int h = 0; h < 2; h++) {
                *(float2*)(P + (size_t)(row + 8 * h) * S + col) =
                    make_float2(acc[ms][ns][2 * h + 0] * scale,
                                acc[ms][ns][2 * h + 1] * scale);
            }
        }
}

// ---------------------------------------------------------------------------
// 3) causal softmax: g_p fp32 -> g_ph fp16 (zeros up to 128-aligned bound)
// ---------------------------------------------------------------------------
__global__ __launch_bounds__(256) void softmax_kernel() {
    const int r = blockIdx.x;                    // b*S + i
    const int i = r & (S - 1);
    const int jmax = ((i >> 7) + 1) << 7;        // AV reads only j < jmax
    const float* __restrict__ row = g_p + (size_t)r * S;
    const int t = threadIdx.x;

    float v[8];
    float mx = -CUDART_INF_F;
    #pragma unroll
    for (int k = 0; k < 8; k++) {
        const int j = t + k * 256;
        v[k] = (j <= i) ? row[j] : -CUDART_INF_F;
        mx = fmaxf(mx, v[k]);
    }
    __shared__ float red[256];
    red[t] = mx;
    __syncthreads();
    #pragma unroll
    for (int s = 128; s > 0; s >>= 1) {
        if (t < s) red[t] = fmaxf(red[t], red[t + s]);
        __syncthreads();
    }
    mx = red[0];
    __syncthreads();

    float sum = 0.f;
    #pragma unroll
    for (int k = 0; k < 8; k++) { v[k] = __expf(v[k] - mx); sum += v[k]; }
    red[t] = sum;
    __syncthreads();
    #pragma unroll
    for (int s = 128; s > 0; s >>= 1) {
        if (t < s) red[t] += red[t + s];
        __syncthreads();
    }
    const float inv = 1.0f / red[0];

    #pragma unroll
    for (int k = 0; k < 8; k++) {
        const int j = t + k * 256;
        if (j < jmax)
            g_ph[(size_t)r * S + j] = __float2half_rn(v[k] * inv);
    }
}

// ---------------------------------------------------------------------------
// 4) AV GEMM (1-product): out = P @ Vh, causal K bound
// ---------------------------------------------------------------------------
__global__ __launch_bounds__(256, 2) void av_gemm(float* __restrict__ OutAll) {
    const int nt = blockIdx.x, mt = blockIdx.y, b = blockIdx.z;
    const int m0 = mt * 128, n0 = nt * 128;
    const int nchunks = (m0 + 128) / KCHUNK;     // causal bound

    float acc[4][4][4];
    gemm_main<true, false, false>(g_ph + (size_t)b * S * S, (const __half*)nullptr,
                                  S, m0,
                                  g_vh + (size_t)b * S * D, (const __half*)nullptr,
                                  D, n0, nchunks, acc, dynsmem);

    float* __restrict__ O = OutAll + (size_t)b * S * D;
    const int wid = threadIdx.x >> 5, lane = threadIdx.x & 31;
    const int wm = wid >> 2, wn = wid & 3;
    #pragma unroll
    for (int ms = 0; ms < 4; ms++)
        #pragma unroll
        for (int ns = 0; ns < 4; ns++) {
            const int row = m0 + wm * 64 + ms * 16 + (lane >> 2);
            const int col = n0 + wn * 32 + ns * 8 + (lane & 3) * 2;
            #pragma unroll
            for (int h = 0; h < 2; h++) {
                *(float2*)(O + (size_t)(row + 8 * h) * D + col) =
                    make_float2(acc[ms][ns][2 * h + 0], acc[ms][ns][2 * h + 1]);
            }
        }
}

// ---------------------------------------------------------------------------
extern "C" void kernel_launch(void* const* d_in, const int* in_sizes, int n_in,
                              void* d_out, int out_size)
{
    const float* x  = (const float*)d_in[0];
    const float* Wq = (const float*)d_in[1];
    const float* Wk = (const float*)d_in[2];
    const float* Wv = (const float*)d_in[3];
    float* out      = (float*)d_out;

    cudaFuncSetAttribute(qkv_gemm,    cudaFuncAttributeMaxDynamicSharedMemorySize, SMEM_BYTES);
    cudaFuncSetAttribute(scores_gemm, cudaFuncAttributeMaxDynamicSharedMemorySize, SMEM_BYTES);
    cudaFuncSetAttribute(av_gemm,     cudaFuncAttributeMaxDynamicSharedMemorySize, SMEM_BYTES);

    split_x<<<M1 * D / 4 / 256, 256>>>(x);
    transpose_w<<<dim3(D / 32, D / 32, 3), 256>>>(Wq, Wk, Wv);
    qkv_gemm<<<dim3(3 * D / 128, M1 / 128), 256, SMEM_BYTES>>>();
    scores_gemm<<<dim3(S / 128, S / 128, Bb), 256, SMEM_BYTES>>>();
    softmax_kernel<<<M1, 256>>>();
    av_gemm<<<dim3(D / 128, S / 128, Bb), 256, SMEM_BYTES>>>(out);
}